// round 1
// baseline (speedup 1.0000x reference)
#include <cuda_runtime.h>
#include <cuda_bf16.h>
#include <math.h>

// ---------------- problem constants ----------------
#define BB 2
#define TT 8
#define HH 128
#define WW 128
#define CC 96
#define HEADS 6
#define HD 16
#define NTOK (BB*TT*HH*WW)          // 262144 tokens
#define NWIN (NTOK/128)             // 2048 windows (128 tokens each)
#define NW_MASK 1024                // windows per batch image
#define SCALE 0.25f                 // (96/6)^-0.5 = 1/4

// ---------------- scratch (device globals; no allocs) ----------------
__device__ float g_big[(size_t)NTOK * 384];   // qkv (288) then MLP hidden (384)
__device__ float g_xw [(size_t)NTOK * 96];    // LN1 (windowed) then LN2
__device__ float g_attn[(size_t)NTOK * 96];   // attention output (windowed)
__device__ float g_proj[(size_t)NTOK * 96];   // proj output (windowed)
__device__ float g_y  [(size_t)NTOK * 96];    // first residual (natural layout)

// ---------------- LN kernel (one warp per token) ----------------
// WIN=true: output in window-partitioned order with cyclic shift (-1,-4,-4)
template<bool WIN>
__global__ void ln_kernel(const float* __restrict__ in,
                          const float* __restrict__ g,
                          const float* __restrict__ b,
                          float* __restrict__ out)
{
    int gt   = blockIdx.x * 4 + (threadIdx.x >> 5);   // output token index
    int lane = threadIdx.x & 31;

    size_t src;
    if (WIN) {
        int win = gt >> 7, n = gt & 127;
        int bi = win >> 10, r = win & 1023;
        int tb = r >> 8, hb = (r >> 4) & 15, wb = r & 15;
        int dt = n >> 6, dh = (n >> 3) & 7, dw = n & 7;
        int t = tb * 2 + dt, h = hb * 8 + dh, w = wb * 8 + dw;
        int ti = (t + 1) & 7, hi = (h + 4) & 127, wi = (w + 4) & 127;
        src = ((size_t)((bi * 8 + ti) * 128 + hi)) * 128 + wi;
    } else {
        src = gt;
    }
    const float* row = in + src * 96;
    float v0 = row[lane], v1 = row[lane + 32], v2 = row[lane + 64];
    float s  = v0 + v1 + v2;
    float s2 = v0 * v0 + v1 * v1 + v2 * v2;
    #pragma unroll
    for (int o = 16; o; o >>= 1) {
        s  += __shfl_xor_sync(0xffffffffu, s,  o);
        s2 += __shfl_xor_sync(0xffffffffu, s2, o);
    }
    float mean = s * (1.0f / 96.0f);
    float var  = s2 * (1.0f / 96.0f) - mean * mean;
    float rstd = rsqrtf(var + 1e-5f);
    float* orow = out + (size_t)gt * 96;
    orow[lane]      = (v0 - mean) * rstd * g[lane]      + b[lane];
    orow[lane + 32] = (v1 - mean) * rstd * g[lane + 32] + b[lane + 32];
    orow[lane + 64] = (v2 - mean) * rstd * g[lane + 64] + b[lane + 64];
}

// ---------------- generic GEMM: C[M,N] = A[M,K] @ W[N,K]^T + bias ----------------
// EPI: 0 = bias only, 1 = bias + exact GELU, 2 = bias + residual add (res[M,N])
template<int EPI>
__global__ void gemm_kernel(const float* __restrict__ A,
                            const float* __restrict__ Wt,
                            const float* __restrict__ bias,
                            const float* __restrict__ res,
                            float* __restrict__ C,
                            int M, int N, int K)
{
    __shared__ float As[64][33];
    __shared__ float Bs[32][33];
    const int bm = blockIdx.y * 64;
    const int bn = blockIdx.x * 32;
    const int tid = threadIdx.x;
    const int ty = tid >> 4;   // 0..15 -> 4 rows each
    const int tx = tid & 15;   // 0..15 -> 2 cols each
    float acc[4][2] = {};

    for (int k0 = 0; k0 < K; k0 += 32) {
        #pragma unroll
        for (int i = tid; i < 64 * 32; i += 256)
            As[i >> 5][i & 31] = A[(size_t)(bm + (i >> 5)) * K + k0 + (i & 31)];
        #pragma unroll
        for (int i = tid; i < 32 * 32; i += 256)
            Bs[i >> 5][i & 31] = Wt[(size_t)(bn + (i >> 5)) * K + k0 + (i & 31)];
        __syncthreads();
        #pragma unroll
        for (int kk = 0; kk < 32; kk++) {
            float ar[4], br[2];
            #pragma unroll
            for (int i = 0; i < 4; i++) ar[i] = As[ty * 4 + i][kk];
            br[0] = Bs[tx * 2 + 0][kk];
            br[1] = Bs[tx * 2 + 1][kk];
            #pragma unroll
            for (int i = 0; i < 4; i++)
                #pragma unroll
                for (int j = 0; j < 2; j++)
                    acc[i][j] = fmaf(ar[i], br[j], acc[i][j]);
        }
        __syncthreads();
    }

    #pragma unroll
    for (int i = 0; i < 4; i++) {
        int row = bm + ty * 4 + i;
        #pragma unroll
        for (int j = 0; j < 2; j++) {
            int col = bn + tx * 2 + j;
            float v = acc[i][j] + bias[col];
            if (EPI == 1) {
                v = 0.5f * v * (1.0f + erff(v * 0.70710678118654752f));
            } else if (EPI == 2) {
                v += res[(size_t)row * N + col];
            }
            C[(size_t)row * N + col] = v;
        }
    }
}

// ---------------- attention: one block per (head, window) ----------------
// qkv layout: [win*128+n, 288] with cols [0:96)=q, [96:192)=k, [192:288)=v,
// per-head slice head*16..+16. scores kept in SMEM (stride 129, conflict-free).
__global__ void attn_kernel(const float* __restrict__ qkv,
                            const float* __restrict__ mask,
                            float* __restrict__ out)
{
    extern __shared__ float sm[];
    float* ks = sm;            // 128*16
    float* vs = sm + 2048;     // 128*16
    float* sc = sm + 4096;     // 128 rows, stride 129

    const int head = blockIdx.x;
    const int win  = blockIdx.y;
    const int tid  = threadIdx.x;   // query row
    const float* base = qkv + (size_t)win * 128 * 288;

    for (int i = tid; i < 2048; i += 128) {
        int j = i >> 4, d = i & 15;
        ks[i] = base[j * 288 +  96 + head * 16 + d];
        vs[i] = base[j * 288 + 192 + head * 16 + d];
    }
    float qr[16];
    #pragma unroll
    for (int d = 0; d < 16; d++)
        qr[d] = base[tid * 288 + head * 16 + d] * SCALE;
    __syncthreads();

    float* myrow = sc + tid * 129;
    for (int j = 0; j < 128; j++) {
        float s = 0.0f;
        #pragma unroll
        for (int d = 0; d < 16; d++) s = fmaf(qr[d], ks[j * 16 + d], s);
        myrow[j] = s;
    }
    __syncthreads();

    const float* mrow = mask + (size_t)(win & (NW_MASK - 1)) * 16384;
    for (int i = tid; i < 16384; i += 128)
        sc[(i >> 7) * 129 + (i & 127)] += mrow[i];
    __syncthreads();

    float mx = -1e30f;
    for (int j = 0; j < 128; j++) mx = fmaxf(mx, myrow[j]);
    float sum = 0.0f;
    for (int j = 0; j < 128; j++) {
        float e = __expf(myrow[j] - mx);
        myrow[j] = e;
        sum += e;
    }
    float inv = 1.0f / sum;

    float acc[16] = {};
    for (int j = 0; j < 128; j++) {
        float p = myrow[j];
        #pragma unroll
        for (int d = 0; d < 16; d++) acc[d] = fmaf(p, vs[j * 16 + d], acc[d]);
    }
    float* orow = out + ((size_t)win * 128 + tid) * 96 + head * 16;
    #pragma unroll
    for (int d = 0; d < 16; d++) orow[d] = acc[d] * inv;
}

// ---------------- window reverse + roll(+1,+4,+4) + residual ----------------
__global__ void reverse_residual_kernel(const float* __restrict__ x,
                                        const float* __restrict__ proj,
                                        float* __restrict__ y)
{
    int m    = blockIdx.x * 4 + (threadIdx.x >> 5);   // natural token index
    int lane = threadIdx.x & 31;
    int bi = m >> 17;
    int t  = (m >> 14) & 7;
    int h  = (m >> 7) & 127;
    int w  = m & 127;
    int ts = (t + 7) & 7, hs = (h + 124) & 127, ws = (w + 124) & 127;
    int tb = ts >> 1, dt = ts & 1;
    int hb = hs >> 3, dh = hs & 7;
    int wb = ws >> 3, dw = ws & 7;
    int win = ((bi * 4 + tb) * 16 + hb) * 16 + wb;
    int n   = ((dt << 3) | dh) << 3 | dw;
    const float* prow = proj + ((size_t)win * 128 + n) * 96;
    const float* xrow = x + (size_t)m * 96;
    float* yrow = y + (size_t)m * 96;
    yrow[lane]      = xrow[lane]      + prow[lane];
    yrow[lane + 32] = xrow[lane + 32] + prow[lane + 32];
    yrow[lane + 64] = xrow[lane + 64] + prow[lane + 64];
}

// ---------------- launch ----------------
extern "C" void kernel_launch(void* const* d_in, const int* in_sizes, int n_in,
                              void* d_out, int out_size)
{
    const float* x      = (const float*)d_in[0];
    const float* mask   = (const float*)d_in[1];
    const float* g1     = (const float*)d_in[2];
    const float* b1     = (const float*)d_in[3];
    const float* w_qkv  = (const float*)d_in[4];
    const float* b_qkv  = (const float*)d_in[5];
    const float* w_proj = (const float*)d_in[6];
    const float* b_proj = (const float*)d_in[7];
    const float* g2     = (const float*)d_in[8];
    const float* b2     = (const float*)d_in[9];
    const float* w_fc1  = (const float*)d_in[10];
    const float* b_fc1  = (const float*)d_in[11];
    const float* w_fc2  = (const float*)d_in[12];
    const float* b_fc2  = (const float*)d_in[13];
    float* out = (float*)d_out;

    float *p_big, *p_xw, *p_attn, *p_proj, *p_y;
    cudaGetSymbolAddress((void**)&p_big,  g_big);
    cudaGetSymbolAddress((void**)&p_xw,   g_xw);
    cudaGetSymbolAddress((void**)&p_attn, g_attn);
    cudaGetSymbolAddress((void**)&p_proj, g_proj);
    cudaGetSymbolAddress((void**)&p_y,    g_y);

    const int M = NTOK;
    const int tok_blocks = NTOK / 4;

    // 1) LN1 + cyclic shift + window partition -> g_xw (windowed order)
    ln_kernel<true><<<tok_blocks, 128>>>(x, g1, b1, p_xw);

    // 2) QKV GEMM: (M,96) @ (288,96)^T -> g_big (M,288)
    gemm_kernel<0><<<dim3(288 / 32, M / 64), 256>>>(p_xw, w_qkv, b_qkv, nullptr, p_big, M, 288, 96);

    // 3) attention per (head, window) -> g_attn (windowed, M x 96)
    const int attn_smem = (2048 + 2048 + 128 * 129) * 4;  // 82432 bytes
    cudaFuncSetAttribute(attn_kernel, cudaFuncAttributeMaxDynamicSharedMemorySize, attn_smem);
    attn_kernel<<<dim3(HEADS, NWIN), 128, attn_smem>>>(p_big, mask, p_attn);

    // 4) proj GEMM: (M,96) @ (96,96)^T -> g_proj
    gemm_kernel<0><<<dim3(96 / 32, M / 64), 256>>>(p_attn, w_proj, b_proj, nullptr, p_proj, M, 96, 96);

    // 5) window reverse + roll back + residual -> g_y (natural order)
    reverse_residual_kernel<<<tok_blocks, 128>>>(x, p_proj, p_y);

    // 6) LN2 -> g_xw (natural order)
    ln_kernel<false><<<tok_blocks, 128>>>(p_y, g2, b2, p_xw);

    // 7) fc1 GEMM + GELU: (M,96) @ (384,96)^T -> g_big (M,384)
    gemm_kernel<1><<<dim3(384 / 32, M / 64), 256>>>(p_xw, w_fc1, b_fc1, nullptr, p_big, M, 384, 96);

    // 8) fc2 GEMM + residual(y): (M,384) @ (96,384)^T + y -> out
    gemm_kernel<2><<<dim3(96 / 32, M / 64), 256>>>(p_big, w_fc2, b_fc2, p_y, out, M, 96, 384);
}

// round 3
// speedup vs baseline: 3.8230x; 3.8230x over previous
#include <cuda_runtime.h>
#include <cuda_bf16.h>
#include <math.h>
#include <stdint.h>

// ---------------- problem constants ----------------
#define BB 2
#define TT 8
#define HH 128
#define WW 128
#define CC 96
#define HEADS 6
#define NTOK (BB*TT*HH*WW)          // 262144 tokens
#define NWIN (NTOK/128)             // 2048 windows
#define SCALE 0.25f

// ---------------- scratch (device globals; no allocs) ----------------
__device__ __nv_bfloat16 g_big [(size_t)NTOK * 384]; // qkv(288) then MLP hidden(384)
__device__ __nv_bfloat16 g_ln  [(size_t)NTOK * 96];  // LN1 (windowed) / LN2 output
__device__ __nv_bfloat16 g_attn[(size_t)NTOK * 96];  // attention out (windowed)
__device__ float         g_proj[(size_t)NTOK * 96];  // proj out (windowed, fp32)
__device__ float         g_y   [(size_t)NTOK * 96];  // first residual (natural, fp32)
__device__ __nv_bfloat16 g_wb  [110592];             // bf16 weights

#define WB_QKV  0
#define WB_PROJ 27648
#define WB_FC1  36864
#define WB_FC2  73728

// ---------------- helpers ----------------
static __device__ __forceinline__ uint32_t s2u(const void* p) {
    return (uint32_t)__cvta_generic_to_shared(p);
}

#define LDSM_X4(r0,r1,r2,r3,addr) \
    asm volatile("ldmatrix.sync.aligned.m8n8.x4.shared.b16 {%0,%1,%2,%3}, [%4];" \
        : "=r"(r0),"=r"(r1),"=r"(r2),"=r"(r3) : "r"(addr))

#define MMA_BF16(c,a0,a1,a2,a3,b0,b1) \
    asm volatile("mma.sync.aligned.m16n8k16.row.col.f32.bf16.bf16.f32 " \
        "{%0,%1,%2,%3},{%4,%5,%6,%7},{%8,%9},{%0,%1,%2,%3};" \
        : "+f"(c[0]),"+f"(c[1]),"+f"(c[2]),"+f"(c[3]) \
        : "r"(a0),"r"(a1),"r"(a2),"r"(a3),"r"(b0),"r"(b1))

// ---------------- weight conversion fp32 -> bf16 ----------------
__global__ void convert_w(const float* __restrict__ wq, const float* __restrict__ wp,
                          const float* __restrict__ w1, const float* __restrict__ w2,
                          __nv_bfloat16* __restrict__ out)
{
    int i = blockIdx.x * 256 + threadIdx.x;
    if (i < 27648)       out[i] = __float2bfloat16(wq[i]);
    else if (i < 36864)  out[i] = __float2bfloat16(wp[i - 27648]);
    else if (i < 73728)  out[i] = __float2bfloat16(w1[i - 36864]);
    else if (i < 110592) out[i] = __float2bfloat16(w2[i - 73728]);
}

// ---------------- LN kernel (one warp per token), bf16 output ----------------
// WIN=true: output in window-partitioned order with cyclic shift (-1,-4,-4)
template<bool WIN>
__global__ void ln_kernel(const float* __restrict__ in,
                          const float* __restrict__ g,
                          const float* __restrict__ b,
                          __nv_bfloat16* __restrict__ out)
{
    int gt   = blockIdx.x * 4 + (threadIdx.x >> 5);
    int lane = threadIdx.x & 31;

    size_t src;
    if (WIN) {
        int win = gt >> 7, n = gt & 127;
        int bi = win >> 10, r = win & 1023;
        int tb = r >> 8, hb = (r >> 4) & 15, wb = r & 15;
        int dt = n >> 6, dh = (n >> 3) & 7, dw = n & 7;
        int t = tb * 2 + dt, h = hb * 8 + dh, w = wb * 8 + dw;
        int ti = (t + 1) & 7, hi = (h + 4) & 127, wi = (w + 4) & 127;
        src = ((size_t)((bi * 8 + ti) * 128 + hi)) * 128 + wi;
    } else {
        src = gt;
    }
    const float* row = in + src * 96;
    float v0 = row[lane], v1 = row[lane + 32], v2 = row[lane + 64];
    float s  = v0 + v1 + v2;
    float s2 = v0 * v0 + v1 * v1 + v2 * v2;
    #pragma unroll
    for (int o = 16; o; o >>= 1) {
        s  += __shfl_xor_sync(0xffffffffu, s,  o);
        s2 += __shfl_xor_sync(0xffffffffu, s2, o);
    }
    float mean = s * (1.0f / 96.0f);
    float var  = s2 * (1.0f / 96.0f) - mean * mean;
    float rstd = rsqrtf(var + 1e-5f);
    __nv_bfloat16* orow = out + (size_t)gt * 96;
    orow[lane]      = __float2bfloat16((v0 - mean) * rstd * g[lane]      + b[lane]);
    orow[lane + 32] = __float2bfloat16((v1 - mean) * rstd * g[lane + 32] + b[lane + 32]);
    orow[lane + 64] = __float2bfloat16((v2 - mean) * rstd * g[lane + 64] + b[lane + 64]);
}

// ---------------- bf16 tensor-core GEMM ----------------
// C[M,N] = A[M,K] @ W[N,K]^T + bias, EPI: 0=bias, 1=bias+GELU, 2=bias+residual
// BM=128, BN=32, BK=32, 256 threads = 8 warps (4 m x 2 n), warp tile 32x16.
template<int EPI, typename OUT_T>
__global__ void mma_gemm(const __nv_bfloat16* __restrict__ A,
                         const __nv_bfloat16* __restrict__ W,
                         const float* __restrict__ bias,
                         const float* __restrict__ res,
                         OUT_T* __restrict__ C,
                         int M, int N, int K)
{
    constexpr int STR = 40;  // bf16 elements per smem row (80B: 16B-aligned, LDSM conflict-free)
    __shared__ __nv_bfloat16 As[128 * STR];
    __shared__ __nv_bfloat16 Bs[32 * STR];

    const int tid  = threadIdx.x;
    const int lane = tid & 31;
    const int warp = tid >> 5;
    const int wm = warp >> 1, wn = warp & 1;
    const int bm = blockIdx.y * 128, bn = blockIdx.x * 32;

    float acc[2][2][4] = {};

    // precompute ldmatrix smem addrs (depend only on lane)
    uint32_t a_addr[2][2], b_off[2][2];
    #pragma unroll
    for (int mt = 0; mt < 2; mt++)
        #pragma unroll
        for (int ks = 0; ks < 2; ks++) {
            int row = wm * 32 + mt * 16 + (lane & 15);
            int col = ks * 16 + (lane >> 4) * 8;
            a_addr[mt][ks] = s2u(As + row * STR + col);
        }
    #pragma unroll
    for (int nt = 0; nt < 2; nt++)
        #pragma unroll
        for (int ks = 0; ks < 2; ks++) {
            int nrow = wn * 16 + nt * 8 + (lane >> 2);
            int kcol = ks * 16 + (lane & 3) * 2;
            b_off[nt][ks] = nrow * STR + kcol;
        }

    for (int k0 = 0; k0 < K; k0 += 32) {
        // A tile: 128 rows x 32 cols = 512 granules of 8 bf16; 2 per thread
        #pragma unroll
        for (int g = 0; g < 2; g++) {
            int gi  = tid + g * 256;
            int row = gi >> 2, q = gi & 3;
            uint4 av = *(const uint4*)(A + (size_t)(bm + row) * K + k0 + q * 8);
            *(uint4*)(As + row * STR + q * 8) = av;
        }
        // B tile: 32 rows x 32 cols = 128 granules; threads 0..127
        if (tid < 128) {
            int row = tid >> 2, q = tid & 3;
            uint4 bv = *(const uint4*)(W + (size_t)(bn + row) * K + k0 + q * 8);
            *(uint4*)(Bs + row * STR + q * 8) = bv;
        }
        __syncthreads();

        #pragma unroll
        for (int ks = 0; ks < 2; ks++) {
            uint32_t a[2][4], b[2][2];
            #pragma unroll
            for (int mt = 0; mt < 2; mt++)
                LDSM_X4(a[mt][0], a[mt][1], a[mt][2], a[mt][3], a_addr[mt][ks]);
            #pragma unroll
            for (int nt = 0; nt < 2; nt++) {
                b[nt][0] = *(const uint32_t*)(Bs + b_off[nt][ks]);
                b[nt][1] = *(const uint32_t*)(Bs + b_off[nt][ks] + 8);
            }
            #pragma unroll
            for (int mt = 0; mt < 2; mt++)
                #pragma unroll
                for (int nt = 0; nt < 2; nt++)
                    MMA_BF16(acc[mt][nt], a[mt][0], a[mt][1], a[mt][2], a[mt][3],
                             b[nt][0], b[nt][1]);
        }
        __syncthreads();
    }

    // epilogue
    #pragma unroll
    for (int mt = 0; mt < 2; mt++)
        #pragma unroll
        for (int nt = 0; nt < 2; nt++) {
            int row = bm + wm * 32 + mt * 16 + (lane >> 2);
            int col = bn + wn * 16 + nt * 8 + (lane & 3) * 2;
            float bf0 = bias[col], bf1 = bias[col + 1];
            #pragma unroll
            for (int h = 0; h < 2; h++) {
                int r = row + h * 8;
                float v0 = acc[mt][nt][h * 2 + 0] + bf0;
                float v1 = acc[mt][nt][h * 2 + 1] + bf1;
                if (EPI == 1) {
                    v0 = 0.5f * v0 * (1.0f + erff(v0 * 0.70710678118654752f));
                    v1 = 0.5f * v1 * (1.0f + erff(v1 * 0.70710678118654752f));
                } else if (EPI == 2) {
                    v0 += res[(size_t)r * N + col];
                    v1 += res[(size_t)r * N + col + 1];
                }
                if (sizeof(OUT_T) == 2) {
                    __nv_bfloat162 p;
                    p.x = __float2bfloat16(v0);
                    p.y = __float2bfloat16(v1);
                    *(__nv_bfloat162*)((__nv_bfloat16*)C + (size_t)r * N + col) = p;
                } else {
                    float2 p = make_float2(v0, v1);
                    *(float2*)((float*)C + (size_t)r * N + col) = p;
                }
            }
        }
}

// ---------------- attention: block per (head, window), analytic mask ----------------
__global__ void attn_kernel(const __nv_bfloat16* __restrict__ qkv,
                            __nv_bfloat16* __restrict__ out)
{
    __shared__ float ks[2048];
    __shared__ float vs[2048];
    __shared__ int   lab[128];

    const int head = blockIdx.x;
    const int win  = blockIdx.y;
    const int tid  = threadIdx.x;   // query row
    const __nv_bfloat16* base = qkv + (size_t)win * 128 * 288;
    const int hoff = head * 16;

    // analytic mask region labels (equality-class comparison only)
    {
        int r  = win & 1023;
        int tb = r >> 8, hb = (r >> 4) & 15, wb = r & 15;
        int n = tid;
        int lt = (tb == 3) ? (n >> 6) : 0;          // dt (t=6 vs t=7 regions)
        int lh = (hb == 15) ? ((n >> 5) & 1) : 0;   // dh>=4
        int lw = (wb == 15) ? ((n >> 2) & 1) : 0;   // dw>=4
        lab[tid] = lt | (lh << 1) | (lw << 2);
    }

    // load K, V to smem (fp32)
    for (int i = tid; i < 1024; i += 128) {
        int r = i >> 3, p = (i & 7) * 2;
        __nv_bfloat162 kk = *(const __nv_bfloat162*)(base + (size_t)r * 288 + 96  + hoff + p);
        __nv_bfloat162 vv = *(const __nv_bfloat162*)(base + (size_t)r * 288 + 192 + hoff + p);
        ks[r * 16 + p]     = __bfloat162float(kk.x);
        ks[r * 16 + p + 1] = __bfloat162float(kk.y);
        vs[r * 16 + p]     = __bfloat162float(vv.x);
        vs[r * 16 + p + 1] = __bfloat162float(vv.y);
    }
    float qr[16];
    #pragma unroll
    for (int p = 0; p < 16; p += 2) {
        __nv_bfloat162 qq = *(const __nv_bfloat162*)(base + (size_t)tid * 288 + hoff + p);
        qr[p]     = __bfloat162float(qq.x) * SCALE;
        qr[p + 1] = __bfloat162float(qq.y) * SCALE;
    }
    __syncthreads();

    const int mylab = lab[tid];
    float sum = 0.0f;
    float acc[16] = {};
    for (int j = 0; j < 128; j++) {
        float s = 0.0f;
        #pragma unroll
        for (int d = 0; d < 16; d++) s = fmaf(qr[d], ks[j * 16 + d], s);
        float e = (lab[j] == mylab) ? __expf(s) : 0.0f;  // exp(-100) ~ 0
        sum += e;
        #pragma unroll
        for (int d = 0; d < 16; d++) acc[d] = fmaf(e, vs[j * 16 + d], acc[d]);
    }
    float inv = 1.0f / sum;

    __nv_bfloat16* orow = out + ((size_t)win * 128 + tid) * 96 + hoff;
    #pragma unroll
    for (int d = 0; d < 16; d += 2) {
        __nv_bfloat162 p;
        p.x = __float2bfloat16(acc[d] * inv);
        p.y = __float2bfloat16(acc[d + 1] * inv);
        *(__nv_bfloat162*)(orow + d) = p;
    }
}

// ---------------- window reverse + roll(+1,+4,+4) + residual ----------------
__global__ void reverse_residual_kernel(const float* __restrict__ x,
                                        const float* __restrict__ proj,
                                        float* __restrict__ y)
{
    int m    = blockIdx.x * 4 + (threadIdx.x >> 5);
    int lane = threadIdx.x & 31;
    int bi = m >> 17;
    int t  = (m >> 14) & 7;
    int h  = (m >> 7) & 127;
    int w  = m & 127;
    int ts = (t + 7) & 7, hs = (h + 124) & 127, ws = (w + 124) & 127;
    int tb = ts >> 1, dt = ts & 1;
    int hb = hs >> 3, dh = hs & 7;
    int wb = ws >> 3, dw = ws & 7;
    int win = ((bi * 4 + tb) * 16 + hb) * 16 + wb;
    int n   = ((dt << 3) | dh) << 3 | dw;
    const float* prow = proj + ((size_t)win * 128 + n) * 96;
    const float* xrow = x + (size_t)m * 96;
    float* yrow = y + (size_t)m * 96;
    yrow[lane]      = xrow[lane]      + prow[lane];
    yrow[lane + 32] = xrow[lane + 32] + prow[lane + 32];
    yrow[lane + 64] = xrow[lane + 64] + prow[lane + 64];
}

// ---------------- launch ----------------
extern "C" void kernel_launch(void* const* d_in, const int* in_sizes, int n_in,
                              void* d_out, int out_size)
{
    const float* x      = (const float*)d_in[0];
    const float* g1     = (const float*)d_in[2];
    const float* b1     = (const float*)d_in[3];
    const float* w_qkv  = (const float*)d_in[4];
    const float* b_qkv  = (const float*)d_in[5];
    const float* w_proj = (const float*)d_in[6];
    const float* b_proj = (const float*)d_in[7];
    const float* g2     = (const float*)d_in[8];
    const float* b2     = (const float*)d_in[9];
    const float* w_fc1  = (const float*)d_in[10];
    const float* b_fc1  = (const float*)d_in[11];
    const float* w_fc2  = (const float*)d_in[12];
    const float* b_fc2  = (const float*)d_in[13];
    float* out = (float*)d_out;

    __nv_bfloat16 *p_big, *p_ln, *p_attn, *p_wb;
    float *p_proj, *p_y;
    cudaGetSymbolAddress((void**)&p_big,  g_big);
    cudaGetSymbolAddress((void**)&p_ln,   g_ln);
    cudaGetSymbolAddress((void**)&p_attn, g_attn);
    cudaGetSymbolAddress((void**)&p_proj, g_proj);
    cudaGetSymbolAddress((void**)&p_y,    g_y);
    cudaGetSymbolAddress((void**)&p_wb,   g_wb);

    const int M = NTOK;
    const int tok_blocks = NTOK / 4;

    // 0) weights -> bf16
    convert_w<<<(110592 + 255) / 256, 256>>>(w_qkv, w_proj, w_fc1, w_fc2, p_wb);

    // 1) LN1 + shift + window partition -> g_ln (bf16, windowed)
    ln_kernel<true><<<tok_blocks, 128>>>(x, g1, b1, p_ln);

    // 2) QKV GEMM (bf16 out)
    mma_gemm<0, __nv_bfloat16><<<dim3(288 / 32, M / 128), 256>>>(
        p_ln, p_wb + WB_QKV, b_qkv, nullptr, p_big, M, 288, 96);

    // 3) attention (analytic mask) -> g_attn (bf16)
    attn_kernel<<<dim3(HEADS, NWIN), 128>>>(p_big, p_attn);

    // 4) proj GEMM (fp32 out)
    mma_gemm<0, float><<<dim3(96 / 32, M / 128), 256>>>(
        p_attn, p_wb + WB_PROJ, b_proj, nullptr, p_proj, M, 96, 96);

    // 5) window reverse + roll back + residual -> g_y
    reverse_residual_kernel<<<tok_blocks, 128>>>(x, p_proj, p_y);

    // 6) LN2 -> g_ln (bf16, natural)
    ln_kernel<false><<<tok_blocks, 128>>>(p_y, g2, b2, p_ln);

    // 7) fc1 + GELU (bf16 out)
    mma_gemm<1, __nv_bfloat16><<<dim3(384 / 32, M / 128), 256>>>(
        p_ln, p_wb + WB_FC1, b_fc1, nullptr, p_big, M, 384, 96);

    // 8) fc2 + residual -> out (fp32)
    mma_gemm<2, float><<<dim3(96 / 32, M / 128), 256>>>(
        p_big, p_wb + WB_FC2, b_fc2, p_y, out, M, 96, 384);
}

// round 4
// speedup vs baseline: 5.6919x; 1.4889x over previous
#include <cuda_runtime.h>
#include <cuda_bf16.h>
#include <math.h>
#include <stdint.h>

// ---------------- problem constants ----------------
#define BB 2
#define TT 8
#define HH 128
#define WW 128
#define CC 96
#define HEADS 6
#define NTOK (BB*TT*HH*WW)          // 262144 tokens
#define NWIN (NTOK/128)             // 2048 windows
#define SCALE 0.25f

// ---------------- scratch (device globals; no allocs) ----------------
__device__ __nv_bfloat16 g_big [(size_t)NTOK * 384]; // qkv(288) then MLP hidden(384)
__device__ __nv_bfloat16 g_ln  [(size_t)NTOK * 96];  // LN1 (windowed) / LN2 output
__device__ __nv_bfloat16 g_attn[(size_t)NTOK * 96];  // attention out (windowed)
__device__ float         g_proj[(size_t)NTOK * 96];  // proj out (windowed, fp32)
__device__ float         g_y   [(size_t)NTOK * 96];  // first residual (natural, fp32)
__device__ __nv_bfloat16 g_wb  [110592];             // bf16 weights

#define WB_QKV  0
#define WB_PROJ 27648
#define WB_FC1  36864
#define WB_FC2  73728

// ---------------- helpers ----------------
static __device__ __forceinline__ uint32_t s2u(const void* p) {
    return (uint32_t)__cvta_generic_to_shared(p);
}

#define LDSM_X4(r0,r1,r2,r3,addr) \
    asm volatile("ldmatrix.sync.aligned.m8n8.x4.shared.b16 {%0,%1,%2,%3}, [%4];" \
        : "=r"(r0),"=r"(r1),"=r"(r2),"=r"(r3) : "r"(addr))

#define LDSM_X4_T(r0,r1,r2,r3,addr) \
    asm volatile("ldmatrix.sync.aligned.m8n8.x4.trans.shared.b16 {%0,%1,%2,%3}, [%4];" \
        : "=r"(r0),"=r"(r1),"=r"(r2),"=r"(r3) : "r"(addr))

#define MMA_BF16(c,a0,a1,a2,a3,b0,b1) \
    asm volatile("mma.sync.aligned.m16n8k16.row.col.f32.bf16.bf16.f32 " \
        "{%0,%1,%2,%3},{%4,%5,%6,%7},{%8,%9},{%0,%1,%2,%3};" \
        : "+f"(c[0]),"+f"(c[1]),"+f"(c[2]),"+f"(c[3]) \
        : "r"(a0),"r"(a1),"r"(a2),"r"(a3),"r"(b0),"r"(b1))

// ---------------- weight conversion fp32 -> bf16 ----------------
__global__ void convert_w(const float* __restrict__ wq, const float* __restrict__ wp,
                          const float* __restrict__ w1, const float* __restrict__ w2,
                          __nv_bfloat16* __restrict__ out)
{
    int i = blockIdx.x * 256 + threadIdx.x;
    if (i < 27648)       out[i] = __float2bfloat16(wq[i]);
    else if (i < 36864)  out[i] = __float2bfloat16(wp[i - 27648]);
    else if (i < 73728)  out[i] = __float2bfloat16(w1[i - 36864]);
    else if (i < 110592) out[i] = __float2bfloat16(w2[i - 73728]);
}

// ---------------- LN1 + shift + window partition (one warp per token) ----------------
__global__ void ln1_kernel(const float* __restrict__ in,
                           const float* __restrict__ g,
                           const float* __restrict__ b,
                           __nv_bfloat16* __restrict__ out)
{
    int gt   = blockIdx.x * 4 + (threadIdx.x >> 5);
    int lane = threadIdx.x & 31;

    int win = gt >> 7, n = gt & 127;
    int bi = win >> 10, r = win & 1023;
    int tb = r >> 8, hb = (r >> 4) & 15, wb = r & 15;
    int dt = n >> 6, dh = (n >> 3) & 7, dw = n & 7;
    int t = tb * 2 + dt, h = hb * 8 + dh, w = wb * 8 + dw;
    int ti = (t + 1) & 7, hi = (h + 4) & 127, wi = (w + 4) & 127;
    size_t src = ((size_t)((bi * 8 + ti) * 128 + hi)) * 128 + wi;

    const float* row = in + src * 96;
    float v0 = row[lane], v1 = row[lane + 32], v2 = row[lane + 64];
    float s  = v0 + v1 + v2;
    float s2 = v0 * v0 + v1 * v1 + v2 * v2;
    #pragma unroll
    for (int o = 16; o; o >>= 1) {
        s  += __shfl_xor_sync(0xffffffffu, s,  o);
        s2 += __shfl_xor_sync(0xffffffffu, s2, o);
    }
    float mean = s * (1.0f / 96.0f);
    float var  = s2 * (1.0f / 96.0f) - mean * mean;
    float rstd = rsqrtf(var + 1e-5f);
    __nv_bfloat16* orow = out + (size_t)gt * 96;
    orow[lane]      = __float2bfloat16((v0 - mean) * rstd * g[lane]      + b[lane]);
    orow[lane + 32] = __float2bfloat16((v1 - mean) * rstd * g[lane + 32] + b[lane + 32]);
    orow[lane + 64] = __float2bfloat16((v2 - mean) * rstd * g[lane + 64] + b[lane + 64]);
}

// ---------------- bf16 tensor-core GEMM ----------------
template<int EPI, typename OUT_T>
__global__ void mma_gemm(const __nv_bfloat16* __restrict__ A,
                         const __nv_bfloat16* __restrict__ W,
                         const float* __restrict__ bias,
                         const float* __restrict__ res,
                         OUT_T* __restrict__ C,
                         int M, int N, int K)
{
    constexpr int STR = 40;
    __shared__ __nv_bfloat16 As[128 * STR];
    __shared__ __nv_bfloat16 Bs[32 * STR];

    const int tid  = threadIdx.x;
    const int lane = tid & 31;
    const int warp = tid >> 5;
    const int wm = warp >> 1, wn = warp & 1;
    const int bm = blockIdx.y * 128, bn = blockIdx.x * 32;

    float acc[2][2][4] = {};

    uint32_t a_addr[2][2], b_off[2][2];
    #pragma unroll
    for (int mt = 0; mt < 2; mt++)
        #pragma unroll
        for (int ks = 0; ks < 2; ks++) {
            int row = wm * 32 + mt * 16 + (lane & 15);
            int col = ks * 16 + (lane >> 4) * 8;
            a_addr[mt][ks] = s2u(As + row * STR + col);
        }
    #pragma unroll
    for (int nt = 0; nt < 2; nt++)
        #pragma unroll
        for (int ks = 0; ks < 2; ks++) {
            int nrow = wn * 16 + nt * 8 + (lane >> 2);
            int kcol = ks * 16 + (lane & 3) * 2;
            b_off[nt][ks] = nrow * STR + kcol;
        }

    for (int k0 = 0; k0 < K; k0 += 32) {
        #pragma unroll
        for (int g = 0; g < 2; g++) {
            int gi  = tid + g * 256;
            int row = gi >> 2, q = gi & 3;
            uint4 av = *(const uint4*)(A + (size_t)(bm + row) * K + k0 + q * 8);
            *(uint4*)(As + row * STR + q * 8) = av;
        }
        if (tid < 128) {
            int row = tid >> 2, q = tid & 3;
            uint4 bv = *(const uint4*)(W + (size_t)(bn + row) * K + k0 + q * 8);
            *(uint4*)(Bs + row * STR + q * 8) = bv;
        }
        __syncthreads();

        #pragma unroll
        for (int ks = 0; ks < 2; ks++) {
            uint32_t a[2][4], b[2][2];
            #pragma unroll
            for (int mt = 0; mt < 2; mt++)
                LDSM_X4(a[mt][0], a[mt][1], a[mt][2], a[mt][3], a_addr[mt][ks]);
            #pragma unroll
            for (int nt = 0; nt < 2; nt++) {
                b[nt][0] = *(const uint32_t*)(Bs + b_off[nt][ks]);
                b[nt][1] = *(const uint32_t*)(Bs + b_off[nt][ks] + 8);
            }
            #pragma unroll
            for (int mt = 0; mt < 2; mt++)
                #pragma unroll
                for (int nt = 0; nt < 2; nt++)
                    MMA_BF16(acc[mt][nt], a[mt][0], a[mt][1], a[mt][2], a[mt][3],
                             b[nt][0], b[nt][1]);
        }
        __syncthreads();
    }

    #pragma unroll
    for (int mt = 0; mt < 2; mt++)
        #pragma unroll
        for (int nt = 0; nt < 2; nt++) {
            int row = bm + wm * 32 + mt * 16 + (lane >> 2);
            int col = bn + wn * 16 + nt * 8 + (lane & 3) * 2;
            float bf0 = bias[col], bf1 = bias[col + 1];
            #pragma unroll
            for (int h = 0; h < 2; h++) {
                int r = row + h * 8;
                float v0 = acc[mt][nt][h * 2 + 0] + bf0;
                float v1 = acc[mt][nt][h * 2 + 1] + bf1;
                if (EPI == 1) {
                    v0 = 0.5f * v0 * (1.0f + erff(v0 * 0.70710678118654752f));
                    v1 = 0.5f * v1 * (1.0f + erff(v1 * 0.70710678118654752f));
                } else if (EPI == 2) {
                    v0 += res[(size_t)r * N + col];
                    v1 += res[(size_t)r * N + col + 1];
                }
                if (sizeof(OUT_T) == 2) {
                    __nv_bfloat162 p;
                    p.x = __float2bfloat16(v0);
                    p.y = __float2bfloat16(v1);
                    *(__nv_bfloat162*)((__nv_bfloat16*)C + (size_t)r * N + col) = p;
                } else {
                    float2 p = make_float2(v0, v1);
                    *(float2*)((float*)C + (size_t)r * N + col) = p;
                }
            }
        }
}

// ---------------- MMA attention: block per (head, window) ----------------
// S = Q@K^T (m16n8k16), analytic mask + exp in accum, repack P->A frags, O = P@V.
__global__ void attn_mma_kernel(const __nv_bfloat16* __restrict__ qkv,
                                __nv_bfloat16* __restrict__ out)
{
    constexpr int STR = 24;  // bf16 elements per smem row (48B; conflict-free for ldmatrix)
    __shared__ __nv_bfloat16 Qs[128 * STR];
    __shared__ __nv_bfloat16 Ks[128 * STR];
    __shared__ __nv_bfloat16 Vs[128 * STR];
    __shared__ int lab[128];

    const int head = blockIdx.x;
    const int win  = blockIdx.y;
    const int tid  = threadIdx.x;
    const int lane = tid & 31;
    const int warp = tid >> 5;
    const int warpRow = warp * 32;
    const int hoff = head * 16;
    const __nv_bfloat16* base = qkv + (size_t)win * 128 * 288;

    // load q/k/v head slices (one row per thread, 3 x 32B)
    {
        const __nv_bfloat16* src = base + (size_t)tid * 288 + hoff;
        *(uint4*)(Qs + tid * STR)     = *(const uint4*)(src);
        *(uint4*)(Qs + tid * STR + 8) = *(const uint4*)(src + 8);
        *(uint4*)(Ks + tid * STR)     = *(const uint4*)(src + 96);
        *(uint4*)(Ks + tid * STR + 8) = *(const uint4*)(src + 104);
        *(uint4*)(Vs + tid * STR)     = *(const uint4*)(src + 192);
        *(uint4*)(Vs + tid * STR + 8) = *(const uint4*)(src + 200);
    }
    const int wr = win & 1023;
    const int tb = wr >> 8, hb = (wr >> 4) & 15, wb = wr & 15;
    const bool masked = (tb == 3) || (hb == 15) || (wb == 15);
    {
        int n = tid;
        int lt = (tb == 3) ? (n >> 6) : 0;
        int lh = (hb == 15) ? ((n >> 5) & 1) : 0;
        int lw = (wb == 15) ? ((n >> 2) & 1) : 0;
        lab[n] = lt | (lh << 1) | (lw << 2);
    }
    __syncthreads();

    // ldmatrix base addresses
    const int a_rowoff = (lane & 15);
    const int a_coloff = (lane >> 4) * 8;
    const uint32_t k_addr = s2u(Ks + (((lane >> 4) << 3) + (lane & 7)) * STR + ((lane >> 3) & 1) * 8);
    const uint32_t v_addr = s2u(Vs + (lane & 15) * STR + (lane >> 4) * 8);

    #pragma unroll
    for (int mt = 0; mt < 2; mt++) {
        const int rbase = warpRow + mt * 16 + (lane >> 2);  // accum row (low half)
        uint32_t qa[4];
        {
            uint32_t qaddr = s2u(Qs + (warpRow + mt * 16 + a_rowoff) * STR + a_coloff);
            LDSM_X4(qa[0], qa[1], qa[2], qa[3], qaddr);
        }
        const int lr0 = lab[rbase];
        const int lr1 = lab[rbase + 8];

        float sum0 = 0.0f, sum1 = 0.0f;
        uint32_t p[16][2];

        #pragma unroll
        for (int j2 = 0; j2 < 8; j2++) {
            uint32_t kb[4];
            LDSM_X4(kb[0], kb[1], kb[2], kb[3], k_addr + j2 * (16 * STR * 2));
            float c0[4] = {}, c1[4] = {};
            MMA_BF16(c0, qa[0], qa[1], qa[2], qa[3], kb[0], kb[1]);
            MMA_BF16(c1, qa[0], qa[1], qa[2], qa[3], kb[2], kb[3]);

            #pragma unroll
            for (int half = 0; half < 2; half++) {
                float* c = half ? c1 : c0;
                int j = 2 * j2 + half;
                int col0 = j * 8 + (lane & 3) * 2;
                float e00 = __expf(SCALE * c[0]);
                float e01 = __expf(SCALE * c[1]);
                float e10 = __expf(SCALE * c[2]);
                float e11 = __expf(SCALE * c[3]);
                if (masked) {
                    int lc0 = lab[col0], lc1 = lab[col0 + 1];
                    e00 = (lc0 == lr0) ? e00 : 0.0f;
                    e01 = (lc1 == lr0) ? e01 : 0.0f;
                    e10 = (lc0 == lr1) ? e10 : 0.0f;
                    e11 = (lc1 == lr1) ? e11 : 0.0f;
                }
                __nv_bfloat162 lo = __floats2bfloat162_rn(e00, e01);
                __nv_bfloat162 hi = __floats2bfloat162_rn(e10, e11);
                // sum from the rounded values so normalization matches PV exactly
                sum0 += __low2float(lo) + __high2float(lo);
                sum1 += __low2float(hi) + __high2float(hi);
                p[j][0] = *(uint32_t*)&lo;
                p[j][1] = *(uint32_t*)&hi;
            }
        }
        // row-sum reduction across the 4 lanes of each quad-row
        sum0 += __shfl_xor_sync(0xffffffffu, sum0, 1);
        sum0 += __shfl_xor_sync(0xffffffffu, sum0, 2);
        sum1 += __shfl_xor_sync(0xffffffffu, sum1, 1);
        sum1 += __shfl_xor_sync(0xffffffffu, sum1, 2);
        float inv0 = 1.0f / sum0;
        float inv1 = 1.0f / sum1;

        // O = P @ V
        float o[2][4] = {};
        #pragma unroll
        for (int kc = 0; kc < 8; kc++) {
            uint32_t vb[4];
            LDSM_X4_T(vb[0], vb[1], vb[2], vb[3], v_addr + kc * (16 * STR * 2));
            MMA_BF16(o[0], p[2*kc][0], p[2*kc][1], p[2*kc+1][0], p[2*kc+1][1], vb[0], vb[1]);
            MMA_BF16(o[1], p[2*kc][0], p[2*kc][1], p[2*kc+1][0], p[2*kc+1][1], vb[2], vb[3]);
        }

        // write output
        #pragma unroll
        for (int nt = 0; nt < 2; nt++) {
            int col = hoff + nt * 8 + (lane & 3) * 2;
            size_t r0 = (size_t)win * 128 + rbase;
            __nv_bfloat162 w0 = __floats2bfloat162_rn(o[nt][0] * inv0, o[nt][1] * inv0);
            __nv_bfloat162 w1 = __floats2bfloat162_rn(o[nt][2] * inv1, o[nt][3] * inv1);
            *(__nv_bfloat162*)(out + r0 * 96 + col)       = w0;
            *(__nv_bfloat162*)(out + (r0 + 8) * 96 + col) = w1;
        }
    }
}

// ---------------- fused: window reverse + roll + residual + LN2 ----------------
__global__ void res_ln2_kernel(const float* __restrict__ x,
                               const float* __restrict__ proj,
                               const float* __restrict__ g,
                               const float* __restrict__ b,
                               float* __restrict__ y,
                               __nv_bfloat16* __restrict__ ln)
{
    int m    = blockIdx.x * 4 + (threadIdx.x >> 5);
    int lane = threadIdx.x & 31;
    int bi = m >> 17;
    int t  = (m >> 14) & 7;
    int h  = (m >> 7) & 127;
    int w  = m & 127;
    int ts = (t + 7) & 7, hs = (h + 124) & 127, ws = (w + 124) & 127;
    int tb = ts >> 1, dt = ts & 1;
    int hb = hs >> 3, dh = hs & 7;
    int wb = ws >> 3, dw = ws & 7;
    int win = ((bi * 4 + tb) * 16 + hb) * 16 + wb;
    int n   = ((dt << 3) | dh) << 3 | dw;
    const float* prow = proj + ((size_t)win * 128 + n) * 96;
    const float* xrow = x + (size_t)m * 96;
    float v0 = xrow[lane]      + prow[lane];
    float v1 = xrow[lane + 32] + prow[lane + 32];
    float v2 = xrow[lane + 64] + prow[lane + 64];
    float* yrow = y + (size_t)m * 96;
    yrow[lane]      = v0;
    yrow[lane + 32] = v1;
    yrow[lane + 64] = v2;

    float s  = v0 + v1 + v2;
    float s2 = v0 * v0 + v1 * v1 + v2 * v2;
    #pragma unroll
    for (int o = 16; o; o >>= 1) {
        s  += __shfl_xor_sync(0xffffffffu, s,  o);
        s2 += __shfl_xor_sync(0xffffffffu, s2, o);
    }
    float mean = s * (1.0f / 96.0f);
    float var  = s2 * (1.0f / 96.0f) - mean * mean;
    float rstd = rsqrtf(var + 1e-5f);
    __nv_bfloat16* orow = ln + (size_t)m * 96;
    orow[lane]      = __float2bfloat16((v0 - mean) * rstd * g[lane]      + b[lane]);
    orow[lane + 32] = __float2bfloat16((v1 - mean) * rstd * g[lane + 32] + b[lane + 32]);
    orow[lane + 64] = __float2bfloat16((v2 - mean) * rstd * g[lane + 64] + b[lane + 64]);
}

// ---------------- launch ----------------
extern "C" void kernel_launch(void* const* d_in, const int* in_sizes, int n_in,
                              void* d_out, int out_size)
{
    const float* x      = (const float*)d_in[0];
    const float* g1     = (const float*)d_in[2];
    const float* b1     = (const float*)d_in[3];
    const float* w_qkv  = (const float*)d_in[4];
    const float* b_qkv  = (const float*)d_in[5];
    const float* w_proj = (const float*)d_in[6];
    const float* b_proj = (const float*)d_in[7];
    const float* g2     = (const float*)d_in[8];
    const float* b2     = (const float*)d_in[9];
    const float* w_fc1  = (const float*)d_in[10];
    const float* b_fc1  = (const float*)d_in[11];
    const float* w_fc2  = (const float*)d_in[12];
    const float* b_fc2  = (const float*)d_in[13];
    float* out = (float*)d_out;

    __nv_bfloat16 *p_big, *p_ln, *p_attn, *p_wb;
    float *p_proj, *p_y;
    cudaGetSymbolAddress((void**)&p_big,  g_big);
    cudaGetSymbolAddress((void**)&p_ln,   g_ln);
    cudaGetSymbolAddress((void**)&p_attn, g_attn);
    cudaGetSymbolAddress((void**)&p_proj, g_proj);
    cudaGetSymbolAddress((void**)&p_y,    g_y);
    cudaGetSymbolAddress((void**)&p_wb,   g_wb);

    const int M = NTOK;
    const int tok_blocks = NTOK / 4;

    convert_w<<<(110592 + 255) / 256, 256>>>(w_qkv, w_proj, w_fc1, w_fc2, p_wb);

    ln1_kernel<<<tok_blocks, 128>>>(x, g1, b1, p_ln);

    mma_gemm<0, __nv_bfloat16><<<dim3(288 / 32, M / 128), 256>>>(
        p_ln, p_wb + WB_QKV, b_qkv, nullptr, p_big, M, 288, 96);

    attn_mma_kernel<<<dim3(HEADS, NWIN), 128>>>(p_big, p_attn);

    mma_gemm<0, float><<<dim3(96 / 32, M / 128), 256>>>(
        p_attn, p_wb + WB_PROJ, b_proj, nullptr, p_proj, M, 96, 96);

    res_ln2_kernel<<<tok_blocks, 128>>>(x, p_proj, g2, b2, p_y, p_ln);

    mma_gemm<1, __nv_bfloat16><<<dim3(384 / 32, M / 128), 256>>>(
        p_ln, p_wb + WB_FC1, b_fc1, nullptr, p_big, M, 384, 96);

    mma_gemm<2, float><<<dim3(96 / 32, M / 128), 256>>>(
        p_big, p_wb + WB_FC2, b_fc2, p_y, out, M, 96, 384);
}

// round 5
// speedup vs baseline: 6.7666x; 1.1888x over previous
#include <cuda_runtime.h>
#include <cuda_bf16.h>
#include <math.h>
#include <stdint.h>

// ---------------- problem constants ----------------
#define BB 2
#define TT 8
#define HH 128
#define WW 128
#define CC 96
#define HEADS 6
#define NTOK (BB*TT*HH*WW)          // 262144 tokens
#define NWIN (NTOK/128)             // 2048 windows
#define SCALE 0.25f

// ---------------- scratch (device globals; no allocs) ----------------
__device__ __nv_bfloat16 g_big [(size_t)NTOK * 384]; // qkv(288) then MLP hidden(384)
__device__ __nv_bfloat16 g_ln  [(size_t)NTOK * 96];  // LN1 (windowed) / LN2 output
__device__ __nv_bfloat16 g_attn[(size_t)NTOK * 96];  // attention out (windowed)
__device__ float         g_y   [(size_t)NTOK * 96];  // first residual (natural, fp32)
__device__ __nv_bfloat16 g_wb  [110592];             // bf16 weights

#define WB_QKV  0
#define WB_PROJ 27648
#define WB_FC1  36864
#define WB_FC2  73728

// ---------------- helpers ----------------
static __device__ __forceinline__ uint32_t s2u(const void* p) {
    return (uint32_t)__cvta_generic_to_shared(p);
}

#define LDSM_X4(r0,r1,r2,r3,addr) \
    asm volatile("ldmatrix.sync.aligned.m8n8.x4.shared.b16 {%0,%1,%2,%3}, [%4];" \
        : "=r"(r0),"=r"(r1),"=r"(r2),"=r"(r3) : "r"(addr))

#define LDSM_X4_T(r0,r1,r2,r3,addr) \
    asm volatile("ldmatrix.sync.aligned.m8n8.x4.trans.shared.b16 {%0,%1,%2,%3}, [%4];" \
        : "=r"(r0),"=r"(r1),"=r"(r2),"=r"(r3) : "r"(addr))

#define MMA_BF16(c,a0,a1,a2,a3,b0,b1) \
    asm volatile("mma.sync.aligned.m16n8k16.row.col.f32.bf16.bf16.f32 " \
        "{%0,%1,%2,%3},{%4,%5,%6,%7},{%8,%9},{%0,%1,%2,%3};" \
        : "+f"(c[0]),"+f"(c[1]),"+f"(c[2]),"+f"(c[3]) \
        : "r"(a0),"r"(a1),"r"(a2),"r"(a3),"r"(b0),"r"(b1))

// ---------------- weight conversion fp32 -> bf16 ----------------
__global__ void convert_w(const float* __restrict__ wq, const float* __restrict__ wp,
                          const float* __restrict__ w1, const float* __restrict__ w2,
                          __nv_bfloat16* __restrict__ out)
{
    int i = blockIdx.x * 256 + threadIdx.x;
    if (i < 27648)       out[i] = __float2bfloat16(wq[i]);
    else if (i < 36864)  out[i] = __float2bfloat16(wp[i - 27648]);
    else if (i < 73728)  out[i] = __float2bfloat16(w1[i - 36864]);
    else if (i < 110592) out[i] = __float2bfloat16(w2[i - 73728]);
}

// ---------------- LN1 + shift + window partition (one warp per token) ----------------
__global__ void ln1_kernel(const float* __restrict__ in,
                           const float* __restrict__ g,
                           const float* __restrict__ b,
                           __nv_bfloat16* __restrict__ out)
{
    int gt   = blockIdx.x * 4 + (threadIdx.x >> 5);
    int lane = threadIdx.x & 31;

    int win = gt >> 7, n = gt & 127;
    int bi = win >> 10, r = win & 1023;
    int tb = r >> 8, hb = (r >> 4) & 15, wb = r & 15;
    int dt = n >> 6, dh = (n >> 3) & 7, dw = n & 7;
    int t = tb * 2 + dt, h = hb * 8 + dh, w = wb * 8 + dw;
    int ti = (t + 1) & 7, hi = (h + 4) & 127, wi = (w + 4) & 127;
    size_t src = ((size_t)((bi * 8 + ti) * 128 + hi)) * 128 + wi;

    const float* row = in + src * 96;
    float v0 = row[lane], v1 = row[lane + 32], v2 = row[lane + 64];
    float s  = v0 + v1 + v2;
    float s2 = v0 * v0 + v1 * v1 + v2 * v2;
    #pragma unroll
    for (int o = 16; o; o >>= 1) {
        s  += __shfl_xor_sync(0xffffffffu, s,  o);
        s2 += __shfl_xor_sync(0xffffffffu, s2, o);
    }
    float mean = s * (1.0f / 96.0f);
    float var  = s2 * (1.0f / 96.0f) - mean * mean;
    float rstd = rsqrtf(var + 1e-5f);
    __nv_bfloat16* orow = out + (size_t)gt * 96;
    orow[lane]      = __float2bfloat16((v0 - mean) * rstd * g[lane]      + b[lane]);
    orow[lane + 32] = __float2bfloat16((v1 - mean) * rstd * g[lane + 32] + b[lane + 32]);
    orow[lane + 64] = __float2bfloat16((v2 - mean) * rstd * g[lane + 64] + b[lane + 64]);
}

// ---------------- bf16 tensor-core GEMM, BM=128 BN=96 BK=96 ----------------
// C[M,N] = A[M,K] @ W[N,K]^T + bias
// EPI: 0=bias (bf16 out), 1=bias+GELU (bf16 out), 2=bias+residual (fp32 out),
//      3=bias + fused window-reverse+roll+residual+LN2 (writes y fp32 + ln bf16)
// 8 warps = 4(m) x 2(n); warp tile 32x48 (2 m-frags x 6 n-frags).
template<int EPI>
__global__ __launch_bounds__(256) void mma_gemm(
        const __nv_bfloat16* __restrict__ A,
        const __nv_bfloat16* __restrict__ W,
        const float* __restrict__ bias,
        const float* __restrict__ res,   // EPI2
        const float* __restrict__ x,     // EPI3
        const float* __restrict__ lng,   // EPI3
        const float* __restrict__ lnb,   // EPI3
        void* __restrict__ Cout,         // EPI0/1: bf16*, EPI2: float*
        float* __restrict__ yout,        // EPI3
        __nv_bfloat16* __restrict__ lnout,  // EPI3
        int M, int N, int K)
{
    constexpr int STR = 104;             // bf16 stride: 208B = odd multiple of 16 -> LDSM conflict-free
    extern __shared__ __align__(16) char smem_raw[];
    __nv_bfloat16* As = (__nv_bfloat16*)smem_raw;                    // 128 x STR
    __nv_bfloat16* Bs = (__nv_bfloat16*)(smem_raw + 128 * STR * 2);  // 96 x STR
    float* epi = (float*)smem_raw;                                   // EPI3: 128 x 100

    const int tid  = threadIdx.x;
    const int lane = tid & 31;
    const int warp = tid >> 5;
    const int wm = warp >> 1, wn = warp & 1;
    const int bm = blockIdx.y * 128, bn = blockIdx.x * 96;

    float acc[2][6][4] = {};

    const uint32_t a_addr0 = s2u(As + (wm * 32 + (lane & 15)) * STR + (lane >> 4) * 8);
    const uint32_t b_addr0 = s2u(Bs + (wn * 48 + ((lane >> 4) << 3) + (lane & 7)) * STR
                                    + ((lane >> 3) & 1) * 8);

    for (int k0 = 0; k0 < K; k0 += 96) {
        // A tile: 128 x 96 = 1536 granules of 8 bf16
        #pragma unroll
        for (int g = 0; g < 6; g++) {
            int gi = g * 256 + tid;
            int row = gi / 12, q = gi - row * 12;
            uint4 v = *(const uint4*)(A + (size_t)(bm + row) * K + k0 + q * 8);
            *(uint4*)(As + row * STR + q * 8) = v;
        }
        // B tile: 96 x 96 = 1152 granules
        #pragma unroll
        for (int g = 0; g < 5; g++) {
            int gi = g * 256 + tid;
            if (gi < 1152) {
                int row = gi / 12, q = gi - row * 12;
                uint4 v = *(const uint4*)(W + (size_t)(bn + row) * K + k0 + q * 8);
                *(uint4*)(Bs + row * STR + q * 8) = v;
            }
        }
        __syncthreads();

        #pragma unroll
        for (int ks = 0; ks < 6; ks++) {
            uint32_t a[2][4], bf[3][4];
            #pragma unroll
            for (int mt = 0; mt < 2; mt++)
                LDSM_X4(a[mt][0], a[mt][1], a[mt][2], a[mt][3],
                        a_addr0 + mt * (16 * STR * 2) + ks * 32);
            #pragma unroll
            for (int ng = 0; ng < 3; ng++)
                LDSM_X4(bf[ng][0], bf[ng][1], bf[ng][2], bf[ng][3],
                        b_addr0 + ng * (16 * STR * 2) + ks * 32);
            #pragma unroll
            for (int mt = 0; mt < 2; mt++)
                #pragma unroll
                for (int nt = 0; nt < 6; nt++) {
                    int ng = nt >> 1, pr = (nt & 1) * 2;
                    MMA_BF16(acc[mt][nt], a[mt][0], a[mt][1], a[mt][2], a[mt][3],
                             bf[ng][pr], bf[ng][pr + 1]);
                }
        }
        __syncthreads();
    }

    if (EPI != 3) {
        #pragma unroll
        for (int mt = 0; mt < 2; mt++)
            #pragma unroll
            for (int nt = 0; nt < 6; nt++) {
                int row = bm + wm * 32 + mt * 16 + (lane >> 2);
                int col = bn + wn * 48 + nt * 8 + (lane & 3) * 2;
                float bf0 = bias[col], bf1 = bias[col + 1];
                #pragma unroll
                for (int hh = 0; hh < 2; hh++) {
                    int r = row + hh * 8;
                    float v0 = acc[mt][nt][hh * 2 + 0] + bf0;
                    float v1 = acc[mt][nt][hh * 2 + 1] + bf1;
                    if (EPI == 1) {
                        v0 = 0.5f * v0 * (1.0f + erff(v0 * 0.70710678118654752f));
                        v1 = 0.5f * v1 * (1.0f + erff(v1 * 0.70710678118654752f));
                    } else if (EPI == 2) {
                        v0 += res[(size_t)r * N + col];
                        v1 += res[(size_t)r * N + col + 1];
                    }
                    if (EPI == 2) {
                        *(float2*)((float*)Cout + (size_t)r * N + col) = make_float2(v0, v1);
                    } else {
                        __nv_bfloat162 p;
                        p.x = __float2bfloat16(v0);
                        p.y = __float2bfloat16(v1);
                        *(__nv_bfloat162*)((__nv_bfloat16*)Cout + (size_t)r * N + col) = p;
                    }
                }
            }
    } else {
        // stage acc (+bias) to smem fp32, stride 100
        #pragma unroll
        for (int mt = 0; mt < 2; mt++)
            #pragma unroll
            for (int nt = 0; nt < 6; nt++) {
                int lr = wm * 32 + mt * 16 + (lane >> 2);
                int lc = wn * 48 + nt * 8 + (lane & 3) * 2;
                float bf0 = bias[lc], bf1 = bias[lc + 1];
                epi[lr * 100 + lc]           = acc[mt][nt][0] + bf0;
                epi[lr * 100 + lc + 1]       = acc[mt][nt][1] + bf1;
                epi[(lr + 8) * 100 + lc]     = acc[mt][nt][2] + bf0;
                epi[(lr + 8) * 100 + lc + 1] = acc[mt][nt][3] + bf1;
            }
        __syncthreads();

        // each warp: 16 rows; residual + LN2, scatter to natural order
        for (int i = 0; i < 16; i++) {
            int lr = warp * 16 + i;
            int gm = bm + lr;                 // windowed token index
            int win = gm >> 7, n = gm & 127;
            int bi = win >> 10, r = win & 1023;
            int tb = r >> 8, hb = (r >> 4) & 15, wb = r & 15;
            int dt = n >> 6, dh = (n >> 3) & 7, dw = n & 7;
            int t = tb * 2 + dt, h = hb * 8 + dh, w = wb * 8 + dw;
            int ti = (t + 1) & 7, hi = (h + 4) & 127, wi = (w + 4) & 127;
            size_t m = ((size_t)((bi * 8 + ti) * 128 + hi)) * 128 + wi;

            const float* xrow = x + m * 96;
            float v0 = epi[lr * 100 + lane]      + xrow[lane];
            float v1 = epi[lr * 100 + lane + 32] + xrow[lane + 32];
            float v2 = epi[lr * 100 + lane + 64] + xrow[lane + 64];
            float* yrow = yout + m * 96;
            yrow[lane]      = v0;
            yrow[lane + 32] = v1;
            yrow[lane + 64] = v2;

            float s  = v0 + v1 + v2;
            float s2 = v0 * v0 + v1 * v1 + v2 * v2;
            #pragma unroll
            for (int o = 16; o; o >>= 1) {
                s  += __shfl_xor_sync(0xffffffffu, s,  o);
                s2 += __shfl_xor_sync(0xffffffffu, s2, o);
            }
            float mean = s * (1.0f / 96.0f);
            float var  = s2 * (1.0f / 96.0f) - mean * mean;
            float rstd = rsqrtf(var + 1e-5f);
            __nv_bfloat16* orow = lnout + m * 96;
            orow[lane]      = __float2bfloat16((v0 - mean) * rstd * lng[lane]      + lnb[lane]);
            orow[lane + 32] = __float2bfloat16((v1 - mean) * rstd * lng[lane + 32] + lnb[lane + 32]);
            orow[lane + 64] = __float2bfloat16((v2 - mean) * rstd * lng[lane + 64] + lnb[lane + 64]);
        }
    }
}

// ---------------- MMA attention: block per (head, window) ----------------
__global__ void attn_mma_kernel(const __nv_bfloat16* __restrict__ qkv,
                                __nv_bfloat16* __restrict__ out)
{
    constexpr int STR = 24;
    __shared__ __nv_bfloat16 Qs[128 * STR];
    __shared__ __nv_bfloat16 Ks[128 * STR];
    __shared__ __nv_bfloat16 Vs[128 * STR];
    __shared__ int lab[128];

    const int head = blockIdx.x;
    const int win  = blockIdx.y;
    const int tid  = threadIdx.x;
    const int lane = tid & 31;
    const int warp = tid >> 5;
    const int warpRow = warp * 32;
    const int hoff = head * 16;
    const __nv_bfloat16* base = qkv + (size_t)win * 128 * 288;

    {
        const __nv_bfloat16* src = base + (size_t)tid * 288 + hoff;
        *(uint4*)(Qs + tid * STR)     = *(const uint4*)(src);
        *(uint4*)(Qs + tid * STR + 8) = *(const uint4*)(src + 8);
        *(uint4*)(Ks + tid * STR)     = *(const uint4*)(src + 96);
        *(uint4*)(Ks + tid * STR + 8) = *(const uint4*)(src + 104);
        *(uint4*)(Vs + tid * STR)     = *(const uint4*)(src + 192);
        *(uint4*)(Vs + tid * STR + 8) = *(const uint4*)(src + 200);
    }
    const int wr = win & 1023;
    const int tb = wr >> 8, hb = (wr >> 4) & 15, wb = wr & 15;
    const bool masked = (tb == 3) || (hb == 15) || (wb == 15);
    {
        int n = tid;
        int lt = (tb == 3) ? (n >> 6) : 0;
        int lh = (hb == 15) ? ((n >> 5) & 1) : 0;
        int lw = (wb == 15) ? ((n >> 2) & 1) : 0;
        lab[n] = lt | (lh << 1) | (lw << 2);
    }
    __syncthreads();

    const int a_rowoff = (lane & 15);
    const int a_coloff = (lane >> 4) * 8;
    const uint32_t k_addr = s2u(Ks + (((lane >> 4) << 3) + (lane & 7)) * STR + ((lane >> 3) & 1) * 8);
    const uint32_t v_addr = s2u(Vs + (lane & 15) * STR + (lane >> 4) * 8);

    #pragma unroll
    for (int mt = 0; mt < 2; mt++) {
        const int rbase = warpRow + mt * 16 + (lane >> 2);
        uint32_t qa[4];
        {
            uint32_t qaddr = s2u(Qs + (warpRow + mt * 16 + a_rowoff) * STR + a_coloff);
            LDSM_X4(qa[0], qa[1], qa[2], qa[3], qaddr);
        }
        const int lr0 = lab[rbase];
        const int lr1 = lab[rbase + 8];

        float sum0 = 0.0f, sum1 = 0.0f;
        uint32_t p[16][2];

        #pragma unroll
        for (int j2 = 0; j2 < 8; j2++) {
            uint32_t kb[4];
            LDSM_X4(kb[0], kb[1], kb[2], kb[3], k_addr + j2 * (16 * STR * 2));
            float c0[4] = {}, c1[4] = {};
            MMA_BF16(c0, qa[0], qa[1], qa[2], qa[3], kb[0], kb[1]);
            MMA_BF16(c1, qa[0], qa[1], qa[2], qa[3], kb[2], kb[3]);

            #pragma unroll
            for (int half = 0; half < 2; half++) {
                float* c = half ? c1 : c0;
                int j = 2 * j2 + half;
                int col0 = j * 8 + (lane & 3) * 2;
                float e00 = __expf(SCALE * c[0]);
                float e01 = __expf(SCALE * c[1]);
                float e10 = __expf(SCALE * c[2]);
                float e11 = __expf(SCALE * c[3]);
                if (masked) {
                    int lc0 = lab[col0], lc1 = lab[col0 + 1];
                    e00 = (lc0 == lr0) ? e00 : 0.0f;
                    e01 = (lc1 == lr0) ? e01 : 0.0f;
                    e10 = (lc0 == lr1) ? e10 : 0.0f;
                    e11 = (lc1 == lr1) ? e11 : 0.0f;
                }
                __nv_bfloat162 lo = __floats2bfloat162_rn(e00, e01);
                __nv_bfloat162 hi = __floats2bfloat162_rn(e10, e11);
                sum0 += __low2float(lo) + __high2float(lo);
                sum1 += __low2float(hi) + __high2float(hi);
                p[j][0] = *(uint32_t*)&lo;
                p[j][1] = *(uint32_t*)&hi;
            }
        }
        sum0 += __shfl_xor_sync(0xffffffffu, sum0, 1);
        sum0 += __shfl_xor_sync(0xffffffffu, sum0, 2);
        sum1 += __shfl_xor_sync(0xffffffffu, sum1, 1);
        sum1 += __shfl_xor_sync(0xffffffffu, sum1, 2);
        float inv0 = 1.0f / sum0;
        float inv1 = 1.0f / sum1;

        float o[2][4] = {};
        #pragma unroll
        for (int kc = 0; kc < 8; kc++) {
            uint32_t vb[4];
            LDSM_X4_T(vb[0], vb[1], vb[2], vb[3], v_addr + kc * (16 * STR * 2));
            MMA_BF16(o[0], p[2*kc][0], p[2*kc][1], p[2*kc+1][0], p[2*kc+1][1], vb[0], vb[1]);
            MMA_BF16(o[1], p[2*kc][0], p[2*kc][1], p[2*kc+1][0], p[2*kc+1][1], vb[2], vb[3]);
        }

        #pragma unroll
        for (int nt = 0; nt < 2; nt++) {
            int col = hoff + nt * 8 + (lane & 3) * 2;
            size_t r0 = (size_t)win * 128 + rbase;
            __nv_bfloat162 w0 = __floats2bfloat162_rn(o[nt][0] * inv0, o[nt][1] * inv0);
            __nv_bfloat162 w1 = __floats2bfloat162_rn(o[nt][2] * inv1, o[nt][3] * inv1);
            *(__nv_bfloat162*)(out + r0 * 96 + col)       = w0;
            *(__nv_bfloat162*)(out + (r0 + 8) * 96 + col) = w1;
        }
    }
}

// ---------------- launch ----------------
extern "C" void kernel_launch(void* const* d_in, const int* in_sizes, int n_in,
                              void* d_out, int out_size)
{
    const float* x      = (const float*)d_in[0];
    const float* g1     = (const float*)d_in[2];
    const float* b1     = (const float*)d_in[3];
    const float* w_qkv  = (const float*)d_in[4];
    const float* b_qkv  = (const float*)d_in[5];
    const float* w_proj = (const float*)d_in[6];
    const float* b_proj = (const float*)d_in[7];
    const float* g2     = (const float*)d_in[8];
    const float* b2     = (const float*)d_in[9];
    const float* w_fc1  = (const float*)d_in[10];
    const float* b_fc1  = (const float*)d_in[11];
    const float* w_fc2  = (const float*)d_in[12];
    const float* b_fc2  = (const float*)d_in[13];
    float* out = (float*)d_out;

    __nv_bfloat16 *p_big, *p_ln, *p_attn, *p_wb;
    float *p_y;
    cudaGetSymbolAddress((void**)&p_big,  g_big);
    cudaGetSymbolAddress((void**)&p_ln,   g_ln);
    cudaGetSymbolAddress((void**)&p_attn, g_attn);
    cudaGetSymbolAddress((void**)&p_y,    g_y);
    cudaGetSymbolAddress((void**)&p_wb,   g_wb);

    const int M = NTOK;
    const int tok_blocks = NTOK / 4;
    const int SMEM_GEMM = (128 + 96) * 104 * 2;   // 46592
    const int SMEM_EPI3 = 128 * 100 * 4;          // 51200
    static bool attr_set = false;
    if (!attr_set) {
        cudaFuncSetAttribute(mma_gemm<3>, cudaFuncAttributeMaxDynamicSharedMemorySize, SMEM_EPI3);
        attr_set = true;
    }

    convert_w<<<(110592 + 255) / 256, 256>>>(w_qkv, w_proj, w_fc1, w_fc2, p_wb);

    ln1_kernel<<<tok_blocks, 128>>>(x, g1, b1, p_ln);

    // QKV: (M,96)@(288,96)^T -> bf16
    mma_gemm<0><<<dim3(3, M / 128), 256, SMEM_GEMM>>>(
        p_ln, p_wb + WB_QKV, b_qkv, nullptr, nullptr, nullptr, nullptr,
        p_big, nullptr, nullptr, M, 288, 96);

    attn_mma_kernel<<<dim3(HEADS, NWIN), 128>>>(p_big, p_attn);

    // proj + fused reverse/residual/LN2: writes y (fp32 natural) + ln (bf16)
    mma_gemm<3><<<dim3(1, M / 128), 256, SMEM_EPI3>>>(
        p_attn, p_wb + WB_PROJ, b_proj, nullptr, x, g2, b2,
        nullptr, p_y, p_ln, M, 96, 96);

    // fc1 + GELU
    mma_gemm<1><<<dim3(4, M / 128), 256, SMEM_GEMM>>>(
        p_ln, p_wb + WB_FC1, b_fc1, nullptr, nullptr, nullptr, nullptr,
        p_big, nullptr, nullptr, M, 384, 96);

    // fc2 + residual -> out
    mma_gemm<2><<<dim3(1, M / 128), 256, SMEM_GEMM>>>(
        p_big, p_wb + WB_FC2, b_fc2, p_y, nullptr, nullptr, nullptr,
        out, nullptr, nullptr, M, 96, 384);
}

// round 6
// speedup vs baseline: 7.7188x; 1.1407x over previous
#include <cuda_runtime.h>
#include <cuda_bf16.h>
#include <math.h>
#include <stdint.h>

// ---------------- problem constants ----------------
#define NTOK (2*8*128*128)          // 262144 tokens
#define NWIN (NTOK/128)             // 2048 windows
#define SCALE 0.25f

// ---------------- scratch ----------------
__device__ __nv_bfloat16 g_big [(size_t)NTOK * 384]; // MLP hidden
__device__ __nv_bfloat16 g_ln  [(size_t)NTOK * 96];  // LN2 output
__device__ float         g_y   [(size_t)NTOK * 96];  // first residual (natural, fp32)
__device__ __nv_bfloat16 g_wb  [110592];             // bf16 weights

#define WB_QKV  0
#define WB_PROJ 27648
#define WB_FC1  36864
#define WB_FC2  73728

static __device__ __forceinline__ uint32_t s2u(const void* p) {
    return (uint32_t)__cvta_generic_to_shared(p);
}

#define LDSM_X4(r0,r1,r2,r3,addr) \
    asm volatile("ldmatrix.sync.aligned.m8n8.x4.shared.b16 {%0,%1,%2,%3}, [%4];" \
        : "=r"(r0),"=r"(r1),"=r"(r2),"=r"(r3) : "r"(addr))

#define LDSM_X4_T(r0,r1,r2,r3,addr) \
    asm volatile("ldmatrix.sync.aligned.m8n8.x4.trans.shared.b16 {%0,%1,%2,%3}, [%4];" \
        : "=r"(r0),"=r"(r1),"=r"(r2),"=r"(r3) : "r"(addr))

#define MMA_BF16(c,a0,a1,a2,a3,b0,b1) \
    asm volatile("mma.sync.aligned.m16n8k16.row.col.f32.bf16.bf16.f32 " \
        "{%0,%1,%2,%3},{%4,%5,%6,%7},{%8,%9},{%0,%1,%2,%3};" \
        : "+f"(c[0]),"+f"(c[1]),"+f"(c[2]),"+f"(c[3]) \
        : "r"(a0),"r"(a1),"r"(a2),"r"(a3),"r"(b0),"r"(b1))

// ---------------- weight conversion fp32 -> bf16 ----------------
__global__ void convert_w(const float* __restrict__ wq, const float* __restrict__ wp,
                          const float* __restrict__ w1, const float* __restrict__ w2,
                          __nv_bfloat16* __restrict__ out)
{
    int i = blockIdx.x * 256 + threadIdx.x;
    if (i < 27648)       out[i] = __float2bfloat16(wq[i]);
    else if (i < 36864)  out[i] = __float2bfloat16(wp[i - 27648]);
    else if (i < 73728)  out[i] = __float2bfloat16(w1[i - 36864]);
    else if (i < 110592) out[i] = __float2bfloat16(w2[i - 73728]);
}

// ================= MEGA attention kernel: one block per window =================
// Phases: LN1+shift gather -> QKV GEMM -> 6-head attention -> proj GEMM
//         -> window-reverse + residual + LN2.
// smem (bf16 elems): sA[128*104] | sW[288*104] | sQKV[128*296] | lab[128 ints]
// epi staging (fp32 128x100) reuses the sQKV region.
#define S_A    0
#define S_W    (128*104)
#define S_QKV  (S_W + 288*104)
#define SMEM_MEGA ((S_QKV + 128*296) * 2 + 512)

__global__ __launch_bounds__(768, 1) void mega_attn_kernel(
    const float* __restrict__ x,
    const float* __restrict__ g1, const float* __restrict__ b1,
    const __nv_bfloat16* __restrict__ wqkv, const float* __restrict__ b_qkv,
    const __nv_bfloat16* __restrict__ wproj, const float* __restrict__ b_proj,
    const float* __restrict__ g2, const float* __restrict__ b2,
    float* __restrict__ yout, __nv_bfloat16* __restrict__ lnout)
{
    extern __shared__ __align__(16) char smem_raw[];
    __nv_bfloat16* sA   = (__nv_bfloat16*)smem_raw;
    __nv_bfloat16* sW   = sA + S_W;
    __nv_bfloat16* sQKV = sA + S_QKV;
    int*   lab = (int*)(sA + S_QKV + 128*296);
    float* epi = (float*)sQKV;   // phase 3/4 staging (51.2KB <= 75.7KB)

    const int win  = blockIdx.x;
    const int tid  = threadIdx.x;
    const int lane = tid & 31;
    const int warp = tid >> 5;

    const int wr = win & 1023;
    const int tb = wr >> 8, hb = (wr >> 4) & 15, wb = wr & 15;

    // ---- phase 0: labels + Wqkv load + LN1 (shift gather) ----
    if (tid < 128) {
        int n = tid;
        int lt = (tb == 3) ? (n >> 6) : 0;
        int lh = (hb == 15) ? ((n >> 5) & 1) : 0;
        int lw = (wb == 15) ? ((n >> 2) & 1) : 0;
        lab[n] = lt | (lh << 1) | (lw << 2);
    }
    for (int gi = tid; gi < 3456; gi += 768) {
        int row = gi / 12, q = gi - row * 12;
        *(uint4*)(sW + row * 104 + q * 8) = *(const uint4*)(wqkv + (size_t)row * 96 + q * 8);
    }
    {
        const int bi = win >> 10;
        for (int tok = warp; tok < 128; tok += 24) {
            int dt = tok >> 6, dh = (tok >> 3) & 7, dw = tok & 7;
            int t = tb * 2 + dt, h = hb * 8 + dh, w = wb * 8 + dw;
            int ti = (t + 1) & 7, hi = (h + 4) & 127, wi = (w + 4) & 127;
            size_t src = ((size_t)((bi * 8 + ti) * 128 + hi)) * 128 + wi;
            const float* row = x + src * 96;
            float v0 = row[lane], v1 = row[lane + 32], v2 = row[lane + 64];
            float s  = v0 + v1 + v2;
            float s2 = v0 * v0 + v1 * v1 + v2 * v2;
            #pragma unroll
            for (int o = 16; o; o >>= 1) {
                s  += __shfl_xor_sync(0xffffffffu, s,  o);
                s2 += __shfl_xor_sync(0xffffffffu, s2, o);
            }
            float mean = s * (1.0f / 96.0f);
            float var  = s2 * (1.0f / 96.0f) - mean * mean;
            float rstd = rsqrtf(var + 1e-5f);
            __nv_bfloat16* orow = sA + tok * 104;
            orow[lane]      = __float2bfloat16((v0 - mean) * rstd * g1[lane]      + b1[lane]);
            orow[lane + 32] = __float2bfloat16((v1 - mean) * rstd * g1[lane + 32] + b1[lane + 32]);
            orow[lane + 64] = __float2bfloat16((v2 - mean) * rstd * g1[lane + 64] + b1[lane + 64]);
        }
    }
    __syncthreads();

    // ---- phase 1: QKV GEMM (128x96)@(288x96)^T -> sQKV (+bias) ----
    {
        const int wm = warp & 3, wn = warp >> 2;   // 4m x 6n
        float acc[2][6][4] = {};
        const uint32_t a0 = s2u(sA + (wm * 32 + (lane & 15)) * 104 + (lane >> 4) * 8);
        const uint32_t b0 = s2u(sW + (wn * 48 + ((lane >> 4) << 3) + (lane & 7)) * 104
                                   + ((lane >> 3) & 1) * 8);
        #pragma unroll
        for (int ks = 0; ks < 6; ks++) {
            uint32_t a[2][4], bf[3][4];
            #pragma unroll
            for (int mt = 0; mt < 2; mt++)
                LDSM_X4(a[mt][0], a[mt][1], a[mt][2], a[mt][3],
                        a0 + mt * (16 * 104 * 2) + ks * 32);
            #pragma unroll
            for (int ng = 0; ng < 3; ng++)
                LDSM_X4(bf[ng][0], bf[ng][1], bf[ng][2], bf[ng][3],
                        b0 + ng * (16 * 104 * 2) + ks * 32);
            #pragma unroll
            for (int mt = 0; mt < 2; mt++)
                #pragma unroll
                for (int nt = 0; nt < 6; nt++) {
                    int ng = nt >> 1, pr = (nt & 1) * 2;
                    MMA_BF16(acc[mt][nt], a[mt][0], a[mt][1], a[mt][2], a[mt][3],
                             bf[ng][pr], bf[ng][pr + 1]);
                }
        }
        #pragma unroll
        for (int mt = 0; mt < 2; mt++)
            #pragma unroll
            for (int nt = 0; nt < 6; nt++) {
                int row = wm * 32 + mt * 16 + (lane >> 2);
                int col = wn * 48 + nt * 8 + (lane & 3) * 2;
                float bf0 = b_qkv[col], bf1 = b_qkv[col + 1];
                __nv_bfloat162 p0, p1;
                p0.x = __float2bfloat16(acc[mt][nt][0] + bf0);
                p0.y = __float2bfloat16(acc[mt][nt][1] + bf1);
                p1.x = __float2bfloat16(acc[mt][nt][2] + bf0);
                p1.y = __float2bfloat16(acc[mt][nt][3] + bf1);
                *(__nv_bfloat162*)(sQKV + row * 296 + col)       = p0;
                *(__nv_bfloat162*)(sQKV + (row + 8) * 296 + col) = p1;
            }
    }
    __syncthreads();

    // ---- phase 2: attention (6 heads x 4 warps) + Wproj prefetch ----
    for (int gi = tid; gi < 1152; gi += 768) {
        int row = gi / 12, q = gi - row * 12;
        *(uint4*)(sW + row * 104 + q * 8) = *(const uint4*)(wproj + (size_t)row * 96 + q * 8);
    }
    {
        const int head = warp >> 2;
        const int warpRow = (warp & 3) * 32;
        const int hoff = head * 16;
        const bool masked = (tb == 3) || (hb == 15) || (wb == 15);

        #pragma unroll
        for (int mt = 0; mt < 2; mt++) {
            const int rbase = warpRow + mt * 16 + (lane >> 2);
            uint32_t qa[4];
            {
                uint32_t qaddr = s2u(sQKV + (warpRow + mt * 16 + (lane & 15)) * 296
                                          + hoff + (lane >> 4) * 8);
                LDSM_X4(qa[0], qa[1], qa[2], qa[3], qaddr);
            }
            const int lr0 = lab[rbase];
            const int lr1 = lab[rbase + 8];

            float sum0 = 0.0f, sum1 = 0.0f;
            uint32_t p[16][2];

            const uint32_t kaddr0 = s2u(sQKV + (((lane >> 4) << 3) + (lane & 7)) * 296
                                             + 96 + hoff + ((lane >> 3) & 1) * 8);
            #pragma unroll
            for (int j2 = 0; j2 < 8; j2++) {
                uint32_t kb[4];
                LDSM_X4(kb[0], kb[1], kb[2], kb[3], kaddr0 + j2 * (16 * 296 * 2));
                float c0[4] = {}, c1[4] = {};
                MMA_BF16(c0, qa[0], qa[1], qa[2], qa[3], kb[0], kb[1]);
                MMA_BF16(c1, qa[0], qa[1], qa[2], qa[3], kb[2], kb[3]);
                #pragma unroll
                for (int half = 0; half < 2; half++) {
                    float* c = half ? c1 : c0;
                    int j = 2 * j2 + half;
                    int col0 = j * 8 + (lane & 3) * 2;
                    float e00 = __expf(SCALE * c[0]);
                    float e01 = __expf(SCALE * c[1]);
                    float e10 = __expf(SCALE * c[2]);
                    float e11 = __expf(SCALE * c[3]);
                    if (masked) {
                        int lc0 = lab[col0], lc1 = lab[col0 + 1];
                        e00 = (lc0 == lr0) ? e00 : 0.0f;
                        e01 = (lc1 == lr0) ? e01 : 0.0f;
                        e10 = (lc0 == lr1) ? e10 : 0.0f;
                        e11 = (lc1 == lr1) ? e11 : 0.0f;
                    }
                    __nv_bfloat162 lo = __floats2bfloat162_rn(e00, e01);
                    __nv_bfloat162 hi = __floats2bfloat162_rn(e10, e11);
                    sum0 += __low2float(lo) + __high2float(lo);
                    sum1 += __low2float(hi) + __high2float(hi);
                    p[j][0] = *(uint32_t*)&lo;
                    p[j][1] = *(uint32_t*)&hi;
                }
            }
            sum0 += __shfl_xor_sync(0xffffffffu, sum0, 1);
            sum0 += __shfl_xor_sync(0xffffffffu, sum0, 2);
            sum1 += __shfl_xor_sync(0xffffffffu, sum1, 1);
            sum1 += __shfl_xor_sync(0xffffffffu, sum1, 2);
            float inv0 = 1.0f / sum0;
            float inv1 = 1.0f / sum1;

            float o[2][4] = {};
            const uint32_t vaddr0 = s2u(sQKV + (lane & 15) * 296 + 192 + hoff + (lane >> 4) * 8);
            #pragma unroll
            for (int kc = 0; kc < 8; kc++) {
                uint32_t vb[4];
                LDSM_X4_T(vb[0], vb[1], vb[2], vb[3], vaddr0 + kc * (16 * 296 * 2));
                MMA_BF16(o[0], p[2*kc][0], p[2*kc][1], p[2*kc+1][0], p[2*kc+1][1], vb[0], vb[1]);
                MMA_BF16(o[1], p[2*kc][0], p[2*kc][1], p[2*kc+1][0], p[2*kc+1][1], vb[2], vb[3]);
            }
            // O -> sA (bf16, stride 104)
            #pragma unroll
            for (int nt = 0; nt < 2; nt++) {
                int col = hoff + nt * 8 + (lane & 3) * 2;
                __nv_bfloat162 w0 = __floats2bfloat162_rn(o[nt][0] * inv0, o[nt][1] * inv0);
                __nv_bfloat162 w1 = __floats2bfloat162_rn(o[nt][2] * inv1, o[nt][3] * inv1);
                *(__nv_bfloat162*)(sA + rbase * 104 + col)       = w0;
                *(__nv_bfloat162*)(sA + (rbase + 8) * 104 + col) = w1;
            }
        }
    }
    __syncthreads();

    // ---- phase 3: proj GEMM (128x96)@(96x96)^T -> epi staging (fp32 +bias) ----
    {
        const int wm = warp & 3, wn = warp >> 2;   // 4m x 6n, warp tile 32x16
        float acc[2][2][4] = {};
        const uint32_t a0 = s2u(sA + (wm * 32 + (lane & 15)) * 104 + (lane >> 4) * 8);
        const uint32_t b0 = s2u(sW + (wn * 16 + ((lane >> 4) << 3) + (lane & 7)) * 104
                                   + ((lane >> 3) & 1) * 8);
        #pragma unroll
        for (int ks = 0; ks < 6; ks++) {
            uint32_t a[2][4], kb[4];
            #pragma unroll
            for (int mt = 0; mt < 2; mt++)
                LDSM_X4(a[mt][0], a[mt][1], a[mt][2], a[mt][3],
                        a0 + mt * (16 * 104 * 2) + ks * 32);
            LDSM_X4(kb[0], kb[1], kb[2], kb[3], b0 + ks * 32);
            #pragma unroll
            for (int mt = 0; mt < 2; mt++) {
                MMA_BF16(acc[mt][0], a[mt][0], a[mt][1], a[mt][2], a[mt][3], kb[0], kb[1]);
                MMA_BF16(acc[mt][1], a[mt][0], a[mt][1], a[mt][2], a[mt][3], kb[2], kb[3]);
            }
        }
        #pragma unroll
        for (int mt = 0; mt < 2; mt++)
            #pragma unroll
            for (int nt = 0; nt < 2; nt++) {
                int lr = wm * 32 + mt * 16 + (lane >> 2);
                int lc = wn * 16 + nt * 8 + (lane & 3) * 2;
                float bf0 = b_proj[lc], bf1 = b_proj[lc + 1];
                epi[lr * 100 + lc]           = acc[mt][nt][0] + bf0;
                epi[lr * 100 + lc + 1]       = acc[mt][nt][1] + bf1;
                epi[(lr + 8) * 100 + lc]     = acc[mt][nt][2] + bf0;
                epi[(lr + 8) * 100 + lc + 1] = acc[mt][nt][3] + bf1;
            }
    }
    __syncthreads();

    // ---- phase 4: window reverse + roll + residual + LN2 ----
    {
        const int bi = win >> 10;
        for (int lr = warp; lr < 128; lr += 24) {
            int dt = lr >> 6, dh = (lr >> 3) & 7, dw = lr & 7;
            int t = tb * 2 + dt, h = hb * 8 + dh, w = wb * 8 + dw;
            int ti = (t + 1) & 7, hi = (h + 4) & 127, wi = (w + 4) & 127;
            size_t m = ((size_t)((bi * 8 + ti) * 128 + hi)) * 128 + wi;

            const float* xrow = x + m * 96;
            float v0 = epi[lr * 100 + lane]      + xrow[lane];
            float v1 = epi[lr * 100 + lane + 32] + xrow[lane + 32];
            float v2 = epi[lr * 100 + lane + 64] + xrow[lane + 64];
            float* yrow = yout + m * 96;
            yrow[lane]      = v0;
            yrow[lane + 32] = v1;
            yrow[lane + 64] = v2;

            float s  = v0 + v1 + v2;
            float s2 = v0 * v0 + v1 * v1 + v2 * v2;
            #pragma unroll
            for (int o = 16; o; o >>= 1) {
                s  += __shfl_xor_sync(0xffffffffu, s,  o);
                s2 += __shfl_xor_sync(0xffffffffu, s2, o);
            }
            float mean = s * (1.0f / 96.0f);
            float var  = s2 * (1.0f / 96.0f) - mean * mean;
            float rstd = rsqrtf(var + 1e-5f);
            __nv_bfloat16* orow = lnout + m * 96;
            orow[lane]      = __float2bfloat16((v0 - mean) * rstd * g2[lane]      + b2[lane]);
            orow[lane + 32] = __float2bfloat16((v1 - mean) * rstd * g2[lane + 32] + b2[lane + 32]);
            orow[lane + 64] = __float2bfloat16((v2 - mean) * rstd * g2[lane + 64] + b2[lane + 64]);
        }
    }
}

// ---------------- bf16 GEMM for MLP (unchanged from R5) ----------------
// EPI: 1=bias+GELU (bf16 out), 2=bias+residual (fp32 out)
template<int EPI>
__global__ __launch_bounds__(256) void mma_gemm(
        const __nv_bfloat16* __restrict__ A,
        const __nv_bfloat16* __restrict__ W,
        const float* __restrict__ bias,
        const float* __restrict__ res,
        void* __restrict__ Cout,
        int M, int N, int K)
{
    constexpr int STR = 104;
    extern __shared__ __align__(16) char smem_raw[];
    __nv_bfloat16* As = (__nv_bfloat16*)smem_raw;
    __nv_bfloat16* Bs = (__nv_bfloat16*)(smem_raw + 128 * STR * 2);

    const int tid  = threadIdx.x;
    const int lane = tid & 31;
    const int warp = tid >> 5;
    const int wm = warp >> 1, wn = warp & 1;
    const int bm = blockIdx.y * 128, bn = blockIdx.x * 96;

    float acc[2][6][4] = {};

    const uint32_t a_addr0 = s2u(As + (wm * 32 + (lane & 15)) * STR + (lane >> 4) * 8);
    const uint32_t b_addr0 = s2u(Bs + (wn * 48 + ((lane >> 4) << 3) + (lane & 7)) * STR
                                    + ((lane >> 3) & 1) * 8);

    for (int k0 = 0; k0 < K; k0 += 96) {
        #pragma unroll
        for (int g = 0; g < 6; g++) {
            int gi = g * 256 + tid;
            int row = gi / 12, q = gi - row * 12;
            uint4 v = *(const uint4*)(A + (size_t)(bm + row) * K + k0 + q * 8);
            *(uint4*)(As + row * STR + q * 8) = v;
        }
        #pragma unroll
        for (int g = 0; g < 5; g++) {
            int gi = g * 256 + tid;
            if (gi < 1152) {
                int row = gi / 12, q = gi - row * 12;
                uint4 v = *(const uint4*)(W + (size_t)(bn + row) * K + k0 + q * 8);
                *(uint4*)(Bs + row * STR + q * 8) = v;
            }
        }
        __syncthreads();

        #pragma unroll
        for (int ks = 0; ks < 6; ks++) {
            uint32_t a[2][4], bf[3][4];
            #pragma unroll
            for (int mt = 0; mt < 2; mt++)
                LDSM_X4(a[mt][0], a[mt][1], a[mt][2], a[mt][3],
                        a_addr0 + mt * (16 * STR * 2) + ks * 32);
            #pragma unroll
            for (int ng = 0; ng < 3; ng++)
                LDSM_X4(bf[ng][0], bf[ng][1], bf[ng][2], bf[ng][3],
                        b_addr0 + ng * (16 * STR * 2) + ks * 32);
            #pragma unroll
            for (int mt = 0; mt < 2; mt++)
                #pragma unroll
                for (int nt = 0; nt < 6; nt++) {
                    int ng = nt >> 1, pr = (nt & 1) * 2;
                    MMA_BF16(acc[mt][nt], a[mt][0], a[mt][1], a[mt][2], a[mt][3],
                             bf[ng][pr], bf[ng][pr + 1]);
                }
        }
        __syncthreads();
    }

    #pragma unroll
    for (int mt = 0; mt < 2; mt++)
        #pragma unroll
        for (int nt = 0; nt < 6; nt++) {
            int row = bm + wm * 32 + mt * 16 + (lane >> 2);
            int col = bn + wn * 48 + nt * 8 + (lane & 3) * 2;
            float bf0 = bias[col], bf1 = bias[col + 1];
            #pragma unroll
            for (int hh = 0; hh < 2; hh++) {
                int r = row + hh * 8;
                float v0 = acc[mt][nt][hh * 2 + 0] + bf0;
                float v1 = acc[mt][nt][hh * 2 + 1] + bf1;
                if (EPI == 1) {
                    v0 = 0.5f * v0 * (1.0f + erff(v0 * 0.70710678118654752f));
                    v1 = 0.5f * v1 * (1.0f + erff(v1 * 0.70710678118654752f));
                } else {
                    v0 += res[(size_t)r * N + col];
                    v1 += res[(size_t)r * N + col + 1];
                }
                if (EPI == 1) {
                    __nv_bfloat162 p;
                    p.x = __float2bfloat16(v0);
                    p.y = __float2bfloat16(v1);
                    *(__nv_bfloat162*)((__nv_bfloat16*)Cout + (size_t)r * N + col) = p;
                } else {
                    *(float2*)((float*)Cout + (size_t)r * N + col) = make_float2(v0, v1);
                }
            }
        }
}

// ---------------- launch ----------------
extern "C" void kernel_launch(void* const* d_in, const int* in_sizes, int n_in,
                              void* d_out, int out_size)
{
    const float* x      = (const float*)d_in[0];
    const float* g1     = (const float*)d_in[2];
    const float* b1     = (const float*)d_in[3];
    const float* w_qkv  = (const float*)d_in[4];
    const float* b_qkv  = (const float*)d_in[5];
    const float* w_proj = (const float*)d_in[6];
    const float* b_proj = (const float*)d_in[7];
    const float* g2     = (const float*)d_in[8];
    const float* b2     = (const float*)d_in[9];
    const float* w_fc1  = (const float*)d_in[10];
    const float* b_fc1  = (const float*)d_in[11];
    const float* w_fc2  = (const float*)d_in[12];
    const float* b_fc2  = (const float*)d_in[13];
    float* out = (float*)d_out;

    __nv_bfloat16 *p_big, *p_ln, *p_wb;
    float *p_y;
    cudaGetSymbolAddress((void**)&p_big, g_big);
    cudaGetSymbolAddress((void**)&p_ln,  g_ln);
    cudaGetSymbolAddress((void**)&p_y,   g_y);
    cudaGetSymbolAddress((void**)&p_wb,  g_wb);

    const int M = NTOK;
    const int SMEM_GEMM = (128 + 96) * 104 * 2;   // 46592
    static bool attr_set = false;
    if (!attr_set) {
        cudaFuncSetAttribute(mega_attn_kernel,
                             cudaFuncAttributeMaxDynamicSharedMemorySize, SMEM_MEGA);
        attr_set = true;
    }

    convert_w<<<(110592 + 255) / 256, 256>>>(w_qkv, w_proj, w_fc1, w_fc2, p_wb);

    // fused: LN1 + QKV + attention + proj + reverse/residual/LN2
    mega_attn_kernel<<<NWIN, 768, SMEM_MEGA>>>(
        x, g1, b1, p_wb + WB_QKV, b_qkv, p_wb + WB_PROJ, b_proj,
        g2, b2, p_y, p_ln);

    // fc1 + GELU
    mma_gemm<1><<<dim3(4, M / 128), 256, SMEM_GEMM>>>(
        p_ln, p_wb + WB_FC1, b_fc1, nullptr, p_big, M, 384, 96);

    // fc2 + residual -> out
    mma_gemm<2><<<dim3(1, M / 128), 256, SMEM_GEMM>>>(
        p_big, p_wb + WB_FC2, b_fc2, p_y, out, M, 96, 384);
}

// round 7
// speedup vs baseline: 8.4115x; 1.0897x over previous
#include <cuda_runtime.h>
#include <cuda_bf16.h>
#include <math.h>
#include <stdint.h>

// ---------------- problem constants ----------------
#define NTOK (2*8*128*128)          // 262144 tokens
#define NWIN (NTOK/128)             // 2048 windows
#define SCALE 0.25f

// ---------------- scratch ----------------
__device__ __nv_bfloat16 g_ln  [(size_t)NTOK * 96];  // LN2 output
__device__ float         g_y   [(size_t)NTOK * 96];  // first residual (natural, fp32)
__device__ __nv_bfloat16 g_wb  [110592];             // bf16 weights

#define WB_QKV  0
#define WB_PROJ 27648
#define WB_FC1  36864
#define WB_FC2  73728

static __device__ __forceinline__ uint32_t s2u(const void* p) {
    return (uint32_t)__cvta_generic_to_shared(p);
}

#define LDSM_X4(r0,r1,r2,r3,addr) \
    asm volatile("ldmatrix.sync.aligned.m8n8.x4.shared.b16 {%0,%1,%2,%3}, [%4];" \
        : "=r"(r0),"=r"(r1),"=r"(r2),"=r"(r3) : "r"(addr))

#define LDSM_X4_T(r0,r1,r2,r3,addr) \
    asm volatile("ldmatrix.sync.aligned.m8n8.x4.trans.shared.b16 {%0,%1,%2,%3}, [%4];" \
        : "=r"(r0),"=r"(r1),"=r"(r2),"=r"(r3) : "r"(addr))

#define MMA_BF16(c,a0,a1,a2,a3,b0,b1) \
    asm volatile("mma.sync.aligned.m16n8k16.row.col.f32.bf16.bf16.f32 " \
        "{%0,%1,%2,%3},{%4,%5,%6,%7},{%8,%9},{%0,%1,%2,%3};" \
        : "+f"(c[0]),"+f"(c[1]),"+f"(c[2]),"+f"(c[3]) \
        : "r"(a0),"r"(a1),"r"(a2),"r"(a3),"r"(b0),"r"(b1))

// ---------------- weight conversion fp32 -> bf16 ----------------
__global__ void convert_w(const float* __restrict__ wq, const float* __restrict__ wp,
                          const float* __restrict__ w1, const float* __restrict__ w2,
                          __nv_bfloat16* __restrict__ out)
{
    int i = blockIdx.x * 256 + threadIdx.x;
    if (i < 27648)       out[i] = __float2bfloat16(wq[i]);
    else if (i < 36864)  out[i] = __float2bfloat16(wp[i - 27648]);
    else if (i < 73728)  out[i] = __float2bfloat16(w1[i - 36864]);
    else if (i < 110592) out[i] = __float2bfloat16(w2[i - 73728]);
}

// ================= MEGA attention kernel: one block per window =================
#define S_A    0
#define S_W    (128*104)
#define S_QKV  (S_W + 288*104)
#define SMEM_MEGA ((S_QKV + 128*296) * 2 + 512)

__global__ __launch_bounds__(768, 1) void mega_attn_kernel(
    const float* __restrict__ x,
    const float* __restrict__ g1, const float* __restrict__ b1,
    const __nv_bfloat16* __restrict__ wqkv, const float* __restrict__ b_qkv,
    const __nv_bfloat16* __restrict__ wproj, const float* __restrict__ b_proj,
    const float* __restrict__ g2, const float* __restrict__ b2,
    float* __restrict__ yout, __nv_bfloat16* __restrict__ lnout)
{
    extern __shared__ __align__(16) char smem_raw[];
    __nv_bfloat16* sA   = (__nv_bfloat16*)smem_raw;
    __nv_bfloat16* sW   = sA + S_W;
    __nv_bfloat16* sQKV = sA + S_QKV;
    int*   lab = (int*)(sA + S_QKV + 128*296);
    float* epi = (float*)sQKV;

    const int win  = blockIdx.x;
    const int tid  = threadIdx.x;
    const int lane = tid & 31;
    const int warp = tid >> 5;

    const int wr = win & 1023;
    const int tb = wr >> 8, hb = (wr >> 4) & 15, wb = wr & 15;

    // ---- phase 0: labels + Wqkv load + LN1 (shift gather) ----
    if (tid < 128) {
        int n = tid;
        int lt = (tb == 3) ? (n >> 6) : 0;
        int lh = (hb == 15) ? ((n >> 5) & 1) : 0;
        int lw = (wb == 15) ? ((n >> 2) & 1) : 0;
        lab[n] = lt | (lh << 1) | (lw << 2);
    }
    for (int gi = tid; gi < 3456; gi += 768) {
        int row = gi / 12, q = gi - row * 12;
        *(uint4*)(sW + row * 104 + q * 8) = *(const uint4*)(wqkv + (size_t)row * 96 + q * 8);
    }
    {
        const int bi = win >> 10;
        for (int tok = warp; tok < 128; tok += 24) {
            int dt = tok >> 6, dh = (tok >> 3) & 7, dw = tok & 7;
            int t = tb * 2 + dt, h = hb * 8 + dh, w = wb * 8 + dw;
            int ti = (t + 1) & 7, hi = (h + 4) & 127, wi = (w + 4) & 127;
            size_t src = ((size_t)((bi * 8 + ti) * 128 + hi)) * 128 + wi;
            const float* row = x + src * 96;
            float v0 = row[lane], v1 = row[lane + 32], v2 = row[lane + 64];
            float s  = v0 + v1 + v2;
            float s2 = v0 * v0 + v1 * v1 + v2 * v2;
            #pragma unroll
            for (int o = 16; o; o >>= 1) {
                s  += __shfl_xor_sync(0xffffffffu, s,  o);
                s2 += __shfl_xor_sync(0xffffffffu, s2, o);
            }
            float mean = s * (1.0f / 96.0f);
            float var  = s2 * (1.0f / 96.0f) - mean * mean;
            float rstd = rsqrtf(var + 1e-5f);
            __nv_bfloat16* orow = sA + tok * 104;
            orow[lane]      = __float2bfloat16((v0 - mean) * rstd * g1[lane]      + b1[lane]);
            orow[lane + 32] = __float2bfloat16((v1 - mean) * rstd * g1[lane + 32] + b1[lane + 32]);
            orow[lane + 64] = __float2bfloat16((v2 - mean) * rstd * g1[lane + 64] + b1[lane + 64]);
        }
    }
    __syncthreads();

    // ---- phase 1: QKV GEMM -> sQKV (+bias) ----
    {
        const int wm = warp & 3, wn = warp >> 2;
        float acc[2][6][4] = {};
        const uint32_t a0 = s2u(sA + (wm * 32 + (lane & 15)) * 104 + (lane >> 4) * 8);
        const uint32_t b0 = s2u(sW + (wn * 48 + ((lane >> 4) << 3) + (lane & 7)) * 104
                                   + ((lane >> 3) & 1) * 8);
        #pragma unroll
        for (int ks = 0; ks < 6; ks++) {
            uint32_t a[2][4], bf[3][4];
            #pragma unroll
            for (int mt = 0; mt < 2; mt++)
                LDSM_X4(a[mt][0], a[mt][1], a[mt][2], a[mt][3],
                        a0 + mt * (16 * 104 * 2) + ks * 32);
            #pragma unroll
            for (int ng = 0; ng < 3; ng++)
                LDSM_X4(bf[ng][0], bf[ng][1], bf[ng][2], bf[ng][3],
                        b0 + ng * (16 * 104 * 2) + ks * 32);
            #pragma unroll
            for (int mt = 0; mt < 2; mt++)
                #pragma unroll
                for (int nt = 0; nt < 6; nt++) {
                    int ng = nt >> 1, pr = (nt & 1) * 2;
                    MMA_BF16(acc[mt][nt], a[mt][0], a[mt][1], a[mt][2], a[mt][3],
                             bf[ng][pr], bf[ng][pr + 1]);
                }
        }
        #pragma unroll
        for (int mt = 0; mt < 2; mt++)
            #pragma unroll
            for (int nt = 0; nt < 6; nt++) {
                int row = wm * 32 + mt * 16 + (lane >> 2);
                int col = wn * 48 + nt * 8 + (lane & 3) * 2;
                float bf0 = b_qkv[col], bf1 = b_qkv[col + 1];
                __nv_bfloat162 p0, p1;
                p0.x = __float2bfloat16(acc[mt][nt][0] + bf0);
                p0.y = __float2bfloat16(acc[mt][nt][1] + bf1);
                p1.x = __float2bfloat16(acc[mt][nt][2] + bf0);
                p1.y = __float2bfloat16(acc[mt][nt][3] + bf1);
                *(__nv_bfloat162*)(sQKV + row * 296 + col)       = p0;
                *(__nv_bfloat162*)(sQKV + (row + 8) * 296 + col) = p1;
            }
    }
    __syncthreads();

    // ---- phase 2: attention (6 heads x 4 warps) + Wproj prefetch ----
    for (int gi = tid; gi < 1152; gi += 768) {
        int row = gi / 12, q = gi - row * 12;
        *(uint4*)(sW + row * 104 + q * 8) = *(const uint4*)(wproj + (size_t)row * 96 + q * 8);
    }
    {
        const int head = warp >> 2;
        const int warpRow = (warp & 3) * 32;
        const int hoff = head * 16;
        const bool masked = (tb == 3) || (hb == 15) || (wb == 15);

        #pragma unroll
        for (int mt = 0; mt < 2; mt++) {
            const int rbase = warpRow + mt * 16 + (lane >> 2);
            uint32_t qa[4];
            {
                uint32_t qaddr = s2u(sQKV + (warpRow + mt * 16 + (lane & 15)) * 296
                                          + hoff + (lane >> 4) * 8);
                LDSM_X4(qa[0], qa[1], qa[2], qa[3], qaddr);
            }
            const int lr0 = lab[rbase];
            const int lr1 = lab[rbase + 8];

            float sum0 = 0.0f, sum1 = 0.0f;
            uint32_t p[16][2];

            const uint32_t kaddr0 = s2u(sQKV + (((lane >> 4) << 3) + (lane & 7)) * 296
                                             + 96 + hoff + ((lane >> 3) & 1) * 8);
            #pragma unroll
            for (int j2 = 0; j2 < 8; j2++) {
                uint32_t kb[4];
                LDSM_X4(kb[0], kb[1], kb[2], kb[3], kaddr0 + j2 * (16 * 296 * 2));
                float c0[4] = {}, c1[4] = {};
                MMA_BF16(c0, qa[0], qa[1], qa[2], qa[3], kb[0], kb[1]);
                MMA_BF16(c1, qa[0], qa[1], qa[2], qa[3], kb[2], kb[3]);
                #pragma unroll
                for (int half = 0; half < 2; half++) {
                    float* c = half ? c1 : c0;
                    int j = 2 * j2 + half;
                    int col0 = j * 8 + (lane & 3) * 2;
                    float e00 = __expf(SCALE * c[0]);
                    float e01 = __expf(SCALE * c[1]);
                    float e10 = __expf(SCALE * c[2]);
                    float e11 = __expf(SCALE * c[3]);
                    if (masked) {
                        int lc0 = lab[col0], lc1 = lab[col0 + 1];
                        e00 = (lc0 == lr0) ? e00 : 0.0f;
                        e01 = (lc1 == lr0) ? e01 : 0.0f;
                        e10 = (lc0 == lr1) ? e10 : 0.0f;
                        e11 = (lc1 == lr1) ? e11 : 0.0f;
                    }
                    __nv_bfloat162 lo = __floats2bfloat162_rn(e00, e01);
                    __nv_bfloat162 hi = __floats2bfloat162_rn(e10, e11);
                    sum0 += __low2float(lo) + __high2float(lo);
                    sum1 += __low2float(hi) + __high2float(hi);
                    p[j][0] = *(uint32_t*)&lo;
                    p[j][1] = *(uint32_t*)&hi;
                }
            }
            sum0 += __shfl_xor_sync(0xffffffffu, sum0, 1);
            sum0 += __shfl_xor_sync(0xffffffffu, sum0, 2);
            sum1 += __shfl_xor_sync(0xffffffffu, sum1, 1);
            sum1 += __shfl_xor_sync(0xffffffffu, sum1, 2);
            float inv0 = 1.0f / sum0;
            float inv1 = 1.0f / sum1;

            float o[2][4] = {};
            const uint32_t vaddr0 = s2u(sQKV + (lane & 15) * 296 + 192 + hoff + (lane >> 4) * 8);
            #pragma unroll
            for (int kc = 0; kc < 8; kc++) {
                uint32_t vb[4];
                LDSM_X4_T(vb[0], vb[1], vb[2], vb[3], vaddr0 + kc * (16 * 296 * 2));
                MMA_BF16(o[0], p[2*kc][0], p[2*kc][1], p[2*kc+1][0], p[2*kc+1][1], vb[0], vb[1]);
                MMA_BF16(o[1], p[2*kc][0], p[2*kc][1], p[2*kc+1][0], p[2*kc+1][1], vb[2], vb[3]);
            }
            #pragma unroll
            for (int nt = 0; nt < 2; nt++) {
                int col = hoff + nt * 8 + (lane & 3) * 2;
                __nv_bfloat162 w0 = __floats2bfloat162_rn(o[nt][0] * inv0, o[nt][1] * inv0);
                __nv_bfloat162 w1 = __floats2bfloat162_rn(o[nt][2] * inv1, o[nt][3] * inv1);
                *(__nv_bfloat162*)(sA + rbase * 104 + col)       = w0;
                *(__nv_bfloat162*)(sA + (rbase + 8) * 104 + col) = w1;
            }
        }
    }
    __syncthreads();

    // ---- phase 3: proj GEMM -> epi staging (fp32 +bias) ----
    {
        const int wm = warp & 3, wn = warp >> 2;
        float acc[2][2][4] = {};
        const uint32_t a0 = s2u(sA + (wm * 32 + (lane & 15)) * 104 + (lane >> 4) * 8);
        const uint32_t b0 = s2u(sW + (wn * 16 + ((lane >> 4) << 3) + (lane & 7)) * 104
                                   + ((lane >> 3) & 1) * 8);
        #pragma unroll
        for (int ks = 0; ks < 6; ks++) {
            uint32_t a[2][4], kb[4];
            #pragma unroll
            for (int mt = 0; mt < 2; mt++)
                LDSM_X4(a[mt][0], a[mt][1], a[mt][2], a[mt][3],
                        a0 + mt * (16 * 104 * 2) + ks * 32);
            LDSM_X4(kb[0], kb[1], kb[2], kb[3], b0 + ks * 32);
            #pragma unroll
            for (int mt = 0; mt < 2; mt++) {
                MMA_BF16(acc[mt][0], a[mt][0], a[mt][1], a[mt][2], a[mt][3], kb[0], kb[1]);
                MMA_BF16(acc[mt][1], a[mt][0], a[mt][1], a[mt][2], a[mt][3], kb[2], kb[3]);
            }
        }
        #pragma unroll
        for (int mt = 0; mt < 2; mt++)
            #pragma unroll
            for (int nt = 0; nt < 2; nt++) {
                int lr = wm * 32 + mt * 16 + (lane >> 2);
                int lc = wn * 16 + nt * 8 + (lane & 3) * 2;
                float bf0 = b_proj[lc], bf1 = b_proj[lc + 1];
                epi[lr * 100 + lc]           = acc[mt][nt][0] + bf0;
                epi[lr * 100 + lc + 1]       = acc[mt][nt][1] + bf1;
                epi[(lr + 8) * 100 + lc]     = acc[mt][nt][2] + bf0;
                epi[(lr + 8) * 100 + lc + 1] = acc[mt][nt][3] + bf1;
            }
    }
    __syncthreads();

    // ---- phase 4: window reverse + roll + residual + LN2 ----
    {
        const int bi = win >> 10;
        for (int lr = warp; lr < 128; lr += 24) {
            int dt = lr >> 6, dh = (lr >> 3) & 7, dw = lr & 7;
            int t = tb * 2 + dt, h = hb * 8 + dh, w = wb * 8 + dw;
            int ti = (t + 1) & 7, hi = (h + 4) & 127, wi = (w + 4) & 127;
            size_t m = ((size_t)((bi * 8 + ti) * 128 + hi)) * 128 + wi;

            const float* xrow = x + m * 96;
            float v0 = epi[lr * 100 + lane]      + xrow[lane];
            float v1 = epi[lr * 100 + lane + 32] + xrow[lane + 32];
            float v2 = epi[lr * 100 + lane + 64] + xrow[lane + 64];
            float* yrow = yout + m * 96;
            yrow[lane]      = v0;
            yrow[lane + 32] = v1;
            yrow[lane + 64] = v2;

            float s  = v0 + v1 + v2;
            float s2 = v0 * v0 + v1 * v1 + v2 * v2;
            #pragma unroll
            for (int o = 16; o; o >>= 1) {
                s  += __shfl_xor_sync(0xffffffffu, s,  o);
                s2 += __shfl_xor_sync(0xffffffffu, s2, o);
            }
            float mean = s * (1.0f / 96.0f);
            float var  = s2 * (1.0f / 96.0f) - mean * mean;
            float rstd = rsqrtf(var + 1e-5f);
            __nv_bfloat16* orow = lnout + m * 96;
            orow[lane]      = __float2bfloat16((v0 - mean) * rstd * g2[lane]      + b2[lane]);
            orow[lane + 32] = __float2bfloat16((v1 - mean) * rstd * g2[lane + 32] + b2[lane + 32]);
            orow[lane + 64] = __float2bfloat16((v2 - mean) * rstd * g2[lane + 64] + b2[lane + 64]);
        }
    }
}

// ================= fused MLP kernel: fc1 + GELU + fc2 + residual =================
// One block per 128 rows. Hidden (128x384 bf16) never leaves smem.
// smem: sLN 128x104 | sH 128x392 | sW 384x104 (W1, then W2 as 96x392)
#define M_LN 0
#define M_H  (128*104)
#define M_W  (M_H + 128*392)
#define SMEM_MLP ((M_W + 384*104) * 2)

__global__ __launch_bounds__(512, 1) void mlp_kernel(
    const __nv_bfloat16* __restrict__ ln,
    const __nv_bfloat16* __restrict__ w1, const float* __restrict__ bias1,
    const __nv_bfloat16* __restrict__ w2, const float* __restrict__ bias2,
    const float* __restrict__ y, float* __restrict__ out)
{
    extern __shared__ __align__(16) char smem_raw[];
    __nv_bfloat16* sLN = (__nv_bfloat16*)smem_raw;
    __nv_bfloat16* sH  = sLN + M_H;
    __nv_bfloat16* sW  = sLN + M_W;

    const int tid  = threadIdx.x;
    const int lane = tid & 31;
    const int warp = tid >> 5;
    const int wm = warp & 7, wn = warp >> 3;   // 8m x 2n
    const size_t bm = (size_t)blockIdx.x * 128;

    // loads: LN tile + W1
    #pragma unroll
    for (int g = 0; g < 3; g++) {
        int gi = g * 512 + tid;
        int row = gi / 12, q = gi - row * 12;
        *(uint4*)(sLN + row * 104 + q * 8) = *(const uint4*)(ln + (bm + row) * 96 + q * 8);
    }
    #pragma unroll
    for (int g = 0; g < 9; g++) {
        int gi = g * 512 + tid;
        int row = gi / 12, q = gi - row * 12;
        *(uint4*)(sW + row * 104 + q * 8) = *(const uint4*)(w1 + (size_t)row * 96 + q * 8);
    }
    __syncthreads();

    // ---- fc1 + GELU -> sH (4 chunks of N=96) ----
    const uint32_t aln = s2u(sLN + (wm * 16 + (lane & 15)) * 104 + (lane >> 4) * 8);
    const uint32_t bw1 = s2u(sW + (wn * 48 + ((lane >> 4) << 3) + (lane & 7)) * 104
                                + ((lane >> 3) & 1) * 8);
    #pragma unroll
    for (int nc = 0; nc < 4; nc++) {
        float acc[6][4] = {};
        #pragma unroll
        for (int ks = 0; ks < 6; ks++) {
            uint32_t a[4], bf[3][4];
            LDSM_X4(a[0], a[1], a[2], a[3], aln + ks * 32);
            #pragma unroll
            for (int ng = 0; ng < 3; ng++)
                LDSM_X4(bf[ng][0], bf[ng][1], bf[ng][2], bf[ng][3],
                        bw1 + (nc * 96 + ng * 16) * (104 * 2) + ks * 32);
            #pragma unroll
            for (int nt = 0; nt < 6; nt++) {
                int ng = nt >> 1, pr = (nt & 1) * 2;
                MMA_BF16(acc[nt], a[0], a[1], a[2], a[3], bf[ng][pr], bf[ng][pr + 1]);
            }
        }
        #pragma unroll
        for (int nt = 0; nt < 6; nt++) {
            int lr  = wm * 16 + (lane >> 2);
            int col = nc * 96 + wn * 48 + nt * 8 + (lane & 3) * 2;
            float bf0 = bias1[col], bf1 = bias1[col + 1];
            float v0 = acc[nt][0] + bf0, v1 = acc[nt][1] + bf1;
            float v2 = acc[nt][2] + bf0, v3 = acc[nt][3] + bf1;
            v0 = 0.5f * v0 * (1.0f + erff(v0 * 0.70710678118654752f));
            v1 = 0.5f * v1 * (1.0f + erff(v1 * 0.70710678118654752f));
            v2 = 0.5f * v2 * (1.0f + erff(v2 * 0.70710678118654752f));
            v3 = 0.5f * v3 * (1.0f + erff(v3 * 0.70710678118654752f));
            __nv_bfloat162 p0, p1;
            p0.x = __float2bfloat16(v0); p0.y = __float2bfloat16(v1);
            p1.x = __float2bfloat16(v2); p1.y = __float2bfloat16(v3);
            *(__nv_bfloat162*)(sH + lr * 392 + col)       = p0;
            *(__nv_bfloat162*)(sH + (lr + 8) * 392 + col) = p1;
        }
    }
    __syncthreads();

    // ---- load W2 (96 x 384, stride 392) over W1 ----
    #pragma unroll
    for (int g = 0; g < 9; g++) {
        int gi = g * 512 + tid;
        int row = gi / 48, q = gi - row * 48;
        *(uint4*)(sW + row * 392 + q * 8) = *(const uint4*)(w2 + (size_t)row * 384 + q * 8);
    }
    __syncthreads();

    // ---- fc2: (128x384)@(96x384)^T + bias + y residual -> out fp32 ----
    float acc[6][4] = {};
    const uint32_t ah  = s2u(sH + (wm * 16 + (lane & 15)) * 392 + (lane >> 4) * 8);
    const uint32_t bw2 = s2u(sW + (wn * 48 + ((lane >> 4) << 3) + (lane & 7)) * 392
                                + ((lane >> 3) & 1) * 8);
    #pragma unroll
    for (int ks = 0; ks < 24; ks++) {
        uint32_t a[4], bf[3][4];
        LDSM_X4(a[0], a[1], a[2], a[3], ah + ks * 32);
        #pragma unroll
        for (int ng = 0; ng < 3; ng++)
            LDSM_X4(bf[ng][0], bf[ng][1], bf[ng][2], bf[ng][3],
                    bw2 + ng * (16 * 392 * 2) + ks * 32);
        #pragma unroll
        for (int nt = 0; nt < 6; nt++) {
            int ng = nt >> 1, pr = (nt & 1) * 2;
            MMA_BF16(acc[nt], a[0], a[1], a[2], a[3], bf[ng][pr], bf[ng][pr + 1]);
        }
    }
    #pragma unroll
    for (int nt = 0; nt < 6; nt++) {
        size_t r = bm + wm * 16 + (lane >> 2);
        int col = wn * 48 + nt * 8 + (lane & 3) * 2;
        float bf0 = bias2[col], bf1 = bias2[col + 1];
        float2 y0 = *(const float2*)(y + r * 96 + col);
        float2 y1 = *(const float2*)(y + (r + 8) * 96 + col);
        *(float2*)(out + r * 96 + col) =
            make_float2(acc[nt][0] + bf0 + y0.x, acc[nt][1] + bf1 + y0.y);
        *(float2*)(out + (r + 8) * 96 + col) =
            make_float2(acc[nt][2] + bf0 + y1.x, acc[nt][3] + bf1 + y1.y);
    }
}

// ---------------- launch ----------------
extern "C" void kernel_launch(void* const* d_in, const int* in_sizes, int n_in,
                              void* d_out, int out_size)
{
    const float* x      = (const float*)d_in[0];
    const float* g1     = (const float*)d_in[2];
    const float* b1     = (const float*)d_in[3];
    const float* w_qkv  = (const float*)d_in[4];
    const float* b_qkv  = (const float*)d_in[5];
    const float* w_proj = (const float*)d_in[6];
    const float* b_proj = (const float*)d_in[7];
    const float* g2     = (const float*)d_in[8];
    const float* b2     = (const float*)d_in[9];
    const float* w_fc1  = (const float*)d_in[10];
    const float* b_fc1  = (const float*)d_in[11];
    const float* w_fc2  = (const float*)d_in[12];
    const float* b_fc2  = (const float*)d_in[13];
    float* out = (float*)d_out;

    __nv_bfloat16 *p_ln, *p_wb;
    float *p_y;
    cudaGetSymbolAddress((void**)&p_ln,  g_ln);
    cudaGetSymbolAddress((void**)&p_y,   g_y);
    cudaGetSymbolAddress((void**)&p_wb,  g_wb);

    static bool attr_set = false;
    if (!attr_set) {
        cudaFuncSetAttribute(mega_attn_kernel,
                             cudaFuncAttributeMaxDynamicSharedMemorySize, SMEM_MEGA);
        cudaFuncSetAttribute(mlp_kernel,
                             cudaFuncAttributeMaxDynamicSharedMemorySize, SMEM_MLP);
        attr_set = true;
    }

    convert_w<<<(110592 + 255) / 256, 256>>>(w_qkv, w_proj, w_fc1, w_fc2, p_wb);

    // fused: LN1 + QKV + attention + proj + reverse/residual/LN2
    mega_attn_kernel<<<NWIN, 768, SMEM_MEGA>>>(
        x, g1, b1, p_wb + WB_QKV, b_qkv, p_wb + WB_PROJ, b_proj,
        g2, b2, p_y, p_ln);

    // fused MLP: fc1 + GELU + fc2 + residual -> out
    mlp_kernel<<<NTOK / 128, 512, SMEM_MLP>>>(
        p_ln, p_wb + WB_FC1, b_fc1, p_wb + WB_FC2, b_fc2, p_y, out);
}

// round 8
// speedup vs baseline: 8.7473x; 1.0399x over previous
#include <cuda_runtime.h>
#include <cuda_bf16.h>
#include <math.h>
#include <stdint.h>

// ---------------- problem constants ----------------
#define NTOK (2*8*128*128)          // 262144 tokens
#define NWIN (NTOK/128)             // 2048 windows
#define SCALE 0.25f

// ---------------- scratch ----------------
__device__ __nv_bfloat16 g_wb [110592];              // bf16 weights

#define WB_QKV  0
#define WB_PROJ 27648
#define WB_FC1  36864
#define WB_FC2  73728

static __device__ __forceinline__ uint32_t s2u(const void* p) {
    return (uint32_t)__cvta_generic_to_shared(p);
}

#define LDSM_X4(r0,r1,r2,r3,addr) \
    asm volatile("ldmatrix.sync.aligned.m8n8.x4.shared.b16 {%0,%1,%2,%3}, [%4];" \
        : "=r"(r0),"=r"(r1),"=r"(r2),"=r"(r3) : "r"(addr))

#define LDSM_X4_T(r0,r1,r2,r3,addr) \
    asm volatile("ldmatrix.sync.aligned.m8n8.x4.trans.shared.b16 {%0,%1,%2,%3}, [%4];" \
        : "=r"(r0),"=r"(r1),"=r"(r2),"=r"(r3) : "r"(addr))

#define MMA_BF16(c,a0,a1,a2,a3,b0,b1) \
    asm volatile("mma.sync.aligned.m16n8k16.row.col.f32.bf16.bf16.f32 " \
        "{%0,%1,%2,%3},{%4,%5,%6,%7},{%8,%9},{%0,%1,%2,%3};" \
        : "+f"(c[0]),"+f"(c[1]),"+f"(c[2]),"+f"(c[3]) \
        : "r"(a0),"r"(a1),"r"(a2),"r"(a3),"r"(b0),"r"(b1))

// ---------------- weight conversion fp32 -> bf16 ----------------
__global__ void convert_w(const float* __restrict__ wq, const float* __restrict__ wp,
                          const float* __restrict__ w1, const float* __restrict__ w2,
                          __nv_bfloat16* __restrict__ out)
{
    int i = blockIdx.x * 256 + threadIdx.x;
    if (i < 27648)       out[i] = __float2bfloat16(wq[i]);
    else if (i < 36864)  out[i] = __float2bfloat16(wp[i - 27648]);
    else if (i < 73728)  out[i] = __float2bfloat16(w1[i - 36864]);
    else if (i < 110592) out[i] = __float2bfloat16(w2[i - 73728]);
}

// ================= MONO kernel: entire Swin block, one CTA per window =================
// smem layout (bf16 element offsets):
//   sA   [0,      13312)  128x104  LN1 out / attn out / LN2 out
//   sW   [13312,  43264)  288x104  Wqkv -> Wproj -> W1 halves (192x104) -> W2 halves (96x200)
//   sQKV [43264,  81152)  128x296  qkv; then y as fp32 128x100 (25600 elems)
//   sHID [68864,  94464)  128x200  MLP hidden half (reuses dead qkv tail)
//   lab  [94464,  94720)  128 ints
#define S_A    0
#define S_W    13312
#define S_QKV  43264
#define S_HID  68864
#define S_LAB  94464
#define SMEM_MONO ((S_LAB + 256) * 2)

__global__ __launch_bounds__(768, 1) void mono_kernel(
    const float* __restrict__ x,
    const float* __restrict__ g1, const float* __restrict__ b1,
    const __nv_bfloat16* __restrict__ wqkv, const float* __restrict__ b_qkv,
    const __nv_bfloat16* __restrict__ wproj, const float* __restrict__ b_proj,
    const float* __restrict__ g2, const float* __restrict__ b2,
    const __nv_bfloat16* __restrict__ w1, const float* __restrict__ bias1,
    const __nv_bfloat16* __restrict__ w2, const float* __restrict__ bias2,
    float* __restrict__ out)
{
    extern __shared__ __align__(16) char smem_raw[];
    __nv_bfloat16* sA   = (__nv_bfloat16*)smem_raw;
    __nv_bfloat16* sW   = sA + S_W;
    __nv_bfloat16* sQKV = sA + S_QKV;
    __nv_bfloat16* sHID = sA + S_HID;
    int*   lab = (int*)(sA + S_LAB);
    float* yep = (float*)sQKV;    // proj staging then y (fp32 128x100)

    const int win  = blockIdx.x;
    const int tid  = threadIdx.x;
    const int lane = tid & 31;
    const int warp = tid >> 5;

    const int wr = win & 1023;
    const int tb = wr >> 8, hb = (wr >> 4) & 15, wb = wr & 15;
    const int bi = win >> 10;

    // ---- phase 0: labels + Wqkv load + LN1 (shift gather) ----
    if (tid < 128) {
        int n = tid;
        int lt = (tb == 3) ? (n >> 6) : 0;
        int lh = (hb == 15) ? ((n >> 5) & 1) : 0;
        int lw = (wb == 15) ? ((n >> 2) & 1) : 0;
        lab[n] = lt | (lh << 1) | (lw << 2);
    }
    for (int gi = tid; gi < 3456; gi += 768) {
        int row = gi / 12, q = gi - row * 12;
        *(uint4*)(sW + row * 104 + q * 8) = *(const uint4*)(wqkv + (size_t)row * 96 + q * 8);
    }
    for (int tok = warp; tok < 128; tok += 24) {
        int dt = tok >> 6, dh = (tok >> 3) & 7, dw = tok & 7;
        int t = tb * 2 + dt, h = hb * 8 + dh, w = wb * 8 + dw;
        int ti = (t + 1) & 7, hi = (h + 4) & 127, wi = (w + 4) & 127;
        size_t src = ((size_t)((bi * 8 + ti) * 128 + hi)) * 128 + wi;
        const float* row = x + src * 96;
        float v0 = row[lane], v1 = row[lane + 32], v2 = row[lane + 64];
        float s  = v0 + v1 + v2;
        float s2 = v0 * v0 + v1 * v1 + v2 * v2;
        #pragma unroll
        for (int o = 16; o; o >>= 1) {
            s  += __shfl_xor_sync(0xffffffffu, s,  o);
            s2 += __shfl_xor_sync(0xffffffffu, s2, o);
        }
        float mean = s * (1.0f / 96.0f);
        float var  = s2 * (1.0f / 96.0f) - mean * mean;
        float rstd = rsqrtf(var + 1e-5f);
        __nv_bfloat16* orow = sA + tok * 104;
        orow[lane]      = __float2bfloat16((v0 - mean) * rstd * g1[lane]      + b1[lane]);
        orow[lane + 32] = __float2bfloat16((v1 - mean) * rstd * g1[lane + 32] + b1[lane + 32]);
        orow[lane + 64] = __float2bfloat16((v2 - mean) * rstd * g1[lane + 64] + b1[lane + 64]);
    }
    __syncthreads();

    // ---- phase 1: QKV GEMM -> sQKV (+bias, bf16) ----
    {
        const int wm = warp & 3, wn = warp >> 2;   // 4m x 6n
        float acc[2][6][4] = {};
        const uint32_t a0 = s2u(sA + (wm * 32 + (lane & 15)) * 104 + (lane >> 4) * 8);
        const uint32_t b0 = s2u(sW + (wn * 48 + ((lane >> 4) << 3) + (lane & 7)) * 104
                                   + ((lane >> 3) & 1) * 8);
        #pragma unroll
        for (int ks = 0; ks < 6; ks++) {
            uint32_t a[2][4], bf[3][4];
            #pragma unroll
            for (int mt = 0; mt < 2; mt++)
                LDSM_X4(a[mt][0], a[mt][1], a[mt][2], a[mt][3],
                        a0 + mt * (16 * 104 * 2) + ks * 32);
            #pragma unroll
            for (int ng = 0; ng < 3; ng++)
                LDSM_X4(bf[ng][0], bf[ng][1], bf[ng][2], bf[ng][3],
                        b0 + ng * (16 * 104 * 2) + ks * 32);
            #pragma unroll
            for (int mt = 0; mt < 2; mt++)
                #pragma unroll
                for (int nt = 0; nt < 6; nt++) {
                    int ng = nt >> 1, pr = (nt & 1) * 2;
                    MMA_BF16(acc[mt][nt], a[mt][0], a[mt][1], a[mt][2], a[mt][3],
                             bf[ng][pr], bf[ng][pr + 1]);
                }
        }
        #pragma unroll
        for (int mt = 0; mt < 2; mt++)
            #pragma unroll
            for (int nt = 0; nt < 6; nt++) {
                int row = wm * 32 + mt * 16 + (lane >> 2);
                int col = wn * 48 + nt * 8 + (lane & 3) * 2;
                float bf0 = b_qkv[col], bf1 = b_qkv[col + 1];
                __nv_bfloat162 p0, p1;
                p0.x = __float2bfloat16(acc[mt][nt][0] + bf0);
                p0.y = __float2bfloat16(acc[mt][nt][1] + bf1);
                p1.x = __float2bfloat16(acc[mt][nt][2] + bf0);
                p1.y = __float2bfloat16(acc[mt][nt][3] + bf1);
                *(__nv_bfloat162*)(sQKV + row * 296 + col)       = p0;
                *(__nv_bfloat162*)(sQKV + (row + 8) * 296 + col) = p1;
            }
    }
    __syncthreads();

    // ---- phase 2: attention (6 heads x 4 warps) + Wproj prefetch ----
    for (int gi = tid; gi < 1152; gi += 768) {
        int row = gi / 12, q = gi - row * 12;
        *(uint4*)(sW + row * 104 + q * 8) = *(const uint4*)(wproj + (size_t)row * 96 + q * 8);
    }
    {
        const int head = warp >> 2;
        const int warpRow = (warp & 3) * 32;
        const int hoff = head * 16;
        const bool masked = (tb == 3) || (hb == 15) || (wb == 15);

        #pragma unroll
        for (int mt = 0; mt < 2; mt++) {
            const int rbase = warpRow + mt * 16 + (lane >> 2);
            uint32_t qa[4];
            {
                uint32_t qaddr = s2u(sQKV + (warpRow + mt * 16 + (lane & 15)) * 296
                                          + hoff + (lane >> 4) * 8);
                LDSM_X4(qa[0], qa[1], qa[2], qa[3], qaddr);
            }
            const int lr0 = lab[rbase];
            const int lr1 = lab[rbase + 8];

            float sum0 = 0.0f, sum1 = 0.0f;
            uint32_t p[16][2];

            const uint32_t kaddr0 = s2u(sQKV + (((lane >> 4) << 3) + (lane & 7)) * 296
                                             + 96 + hoff + ((lane >> 3) & 1) * 8);
            #pragma unroll
            for (int j2 = 0; j2 < 8; j2++) {
                uint32_t kb[4];
                LDSM_X4(kb[0], kb[1], kb[2], kb[3], kaddr0 + j2 * (16 * 296 * 2));
                float c0[4] = {}, c1[4] = {};
                MMA_BF16(c0, qa[0], qa[1], qa[2], qa[3], kb[0], kb[1]);
                MMA_BF16(c1, qa[0], qa[1], qa[2], qa[3], kb[2], kb[3]);
                #pragma unroll
                for (int half = 0; half < 2; half++) {
                    float* c = half ? c1 : c0;
                    int j = 2 * j2 + half;
                    int col0 = j * 8 + (lane & 3) * 2;
                    float e00 = __expf(SCALE * c[0]);
                    float e01 = __expf(SCALE * c[1]);
                    float e10 = __expf(SCALE * c[2]);
                    float e11 = __expf(SCALE * c[3]);
                    if (masked) {
                        int lc0 = lab[col0], lc1 = lab[col0 + 1];
                        e00 = (lc0 == lr0) ? e00 : 0.0f;
                        e01 = (lc1 == lr0) ? e01 : 0.0f;
                        e10 = (lc0 == lr1) ? e10 : 0.0f;
                        e11 = (lc1 == lr1) ? e11 : 0.0f;
                    }
                    __nv_bfloat162 lo = __floats2bfloat162_rn(e00, e01);
                    __nv_bfloat162 hi = __floats2bfloat162_rn(e10, e11);
                    sum0 += __low2float(lo) + __high2float(lo);
                    sum1 += __low2float(hi) + __high2float(hi);
                    p[j][0] = *(uint32_t*)&lo;
                    p[j][1] = *(uint32_t*)&hi;
                }
            }
            sum0 += __shfl_xor_sync(0xffffffffu, sum0, 1);
            sum0 += __shfl_xor_sync(0xffffffffu, sum0, 2);
            sum1 += __shfl_xor_sync(0xffffffffu, sum1, 1);
            sum1 += __shfl_xor_sync(0xffffffffu, sum1, 2);
            float inv0 = 1.0f / sum0;
            float inv1 = 1.0f / sum1;

            float o[2][4] = {};
            const uint32_t vaddr0 = s2u(sQKV + (lane & 15) * 296 + 192 + hoff + (lane >> 4) * 8);
            #pragma unroll
            for (int kc = 0; kc < 8; kc++) {
                uint32_t vb[4];
                LDSM_X4_T(vb[0], vb[1], vb[2], vb[3], vaddr0 + kc * (16 * 296 * 2));
                MMA_BF16(o[0], p[2*kc][0], p[2*kc][1], p[2*kc+1][0], p[2*kc+1][1], vb[0], vb[1]);
                MMA_BF16(o[1], p[2*kc][0], p[2*kc][1], p[2*kc+1][0], p[2*kc+1][1], vb[2], vb[3]);
            }
            #pragma unroll
            for (int nt = 0; nt < 2; nt++) {
                int col = hoff + nt * 8 + (lane & 3) * 2;
                __nv_bfloat162 w0 = __floats2bfloat162_rn(o[nt][0] * inv0, o[nt][1] * inv0);
                __nv_bfloat162 w1 = __floats2bfloat162_rn(o[nt][2] * inv1, o[nt][3] * inv1);
                *(__nv_bfloat162*)(sA + rbase * 104 + col)       = w0;
                *(__nv_bfloat162*)(sA + (rbase + 8) * 104 + col) = w1;
            }
        }
    }
    __syncthreads();

    // ---- phase 3: proj GEMM -> yep staging (fp32 +bias) ----
    {
        const int wm = warp & 3, wn = warp >> 2;
        float acc[2][2][4] = {};
        const uint32_t a0 = s2u(sA + (wm * 32 + (lane & 15)) * 104 + (lane >> 4) * 8);
        const uint32_t b0 = s2u(sW + (wn * 16 + ((lane >> 4) << 3) + (lane & 7)) * 104
                                   + ((lane >> 3) & 1) * 8);
        #pragma unroll
        for (int ks = 0; ks < 6; ks++) {
            uint32_t a[2][4], kb[4];
            #pragma unroll
            for (int mt = 0; mt < 2; mt++)
                LDSM_X4(a[mt][0], a[mt][1], a[mt][2], a[mt][3],
                        a0 + mt * (16 * 104 * 2) + ks * 32);
            LDSM_X4(kb[0], kb[1], kb[2], kb[3], b0 + ks * 32);
            #pragma unroll
            for (int mt = 0; mt < 2; mt++) {
                MMA_BF16(acc[mt][0], a[mt][0], a[mt][1], a[mt][2], a[mt][3], kb[0], kb[1]);
                MMA_BF16(acc[mt][1], a[mt][0], a[mt][1], a[mt][2], a[mt][3], kb[2], kb[3]);
            }
        }
        #pragma unroll
        for (int mt = 0; mt < 2; mt++)
            #pragma unroll
            for (int nt = 0; nt < 2; nt++) {
                int lr = wm * 32 + mt * 16 + (lane >> 2);
                int lc = wn * 16 + nt * 8 + (lane & 3) * 2;
                float bf0 = b_proj[lc], bf1 = b_proj[lc + 1];
                yep[lr * 100 + lc]           = acc[mt][nt][0] + bf0;
                yep[lr * 100 + lc + 1]       = acc[mt][nt][1] + bf1;
                yep[(lr + 8) * 100 + lc]     = acc[mt][nt][2] + bf0;
                yep[(lr + 8) * 100 + lc + 1] = acc[mt][nt][3] + bf1;
            }
    }
    __syncthreads();

    // ---- phase 4: residual (x gather) + LN2; y stays in smem, ln2 -> sA ----
    for (int lr = warp; lr < 128; lr += 24) {
        int dt = lr >> 6, dh = (lr >> 3) & 7, dw = lr & 7;
        int t = tb * 2 + dt, h = hb * 8 + dh, w = wb * 8 + dw;
        int ti = (t + 1) & 7, hi = (h + 4) & 127, wi = (w + 4) & 127;
        size_t m = ((size_t)((bi * 8 + ti) * 128 + hi)) * 128 + wi;

        const float* xrow = x + m * 96;
        float v0 = yep[lr * 100 + lane]      + xrow[lane];
        float v1 = yep[lr * 100 + lane + 32] + xrow[lane + 32];
        float v2 = yep[lr * 100 + lane + 64] + xrow[lane + 64];
        yep[lr * 100 + lane]      = v0;
        yep[lr * 100 + lane + 32] = v1;
        yep[lr * 100 + lane + 64] = v2;

        float s  = v0 + v1 + v2;
        float s2 = v0 * v0 + v1 * v1 + v2 * v2;
        #pragma unroll
        for (int o = 16; o; o >>= 1) {
            s  += __shfl_xor_sync(0xffffffffu, s,  o);
            s2 += __shfl_xor_sync(0xffffffffu, s2, o);
        }
        float mean = s * (1.0f / 96.0f);
        float var  = s2 * (1.0f / 96.0f) - mean * mean;
        float rstd = rsqrtf(var + 1e-5f);
        __nv_bfloat16* orow = sA + lr * 104;
        orow[lane]      = __float2bfloat16((v0 - mean) * rstd * g2[lane]      + b2[lane]);
        orow[lane + 32] = __float2bfloat16((v1 - mean) * rstd * g2[lane + 32] + b2[lane + 32]);
        orow[lane + 64] = __float2bfloat16((v2 - mean) * rstd * g2[lane + 64] + b2[lane + 64]);
    }

    // ---- phase 5: MLP (two halves), fc2 acc in registers ----
    const int wm = warp & 3, wn = warp >> 2;     // 4m x 6n
    float acc2[2][2][4] = {};
    const uint32_t aln = s2u(sA + (wm * 32 + (lane & 15)) * 104 + (lane >> 4) * 8);
    const uint32_t ah  = s2u(sHID + (wm * 32 + (lane & 15)) * 200 + (lane >> 4) * 8);
    const uint32_t bw1 = s2u(sW + (wn * 32 + ((lane >> 4) << 3) + (lane & 7)) * 104
                                + ((lane >> 3) & 1) * 8);
    const uint32_t bw2 = s2u(sW + (wn * 16 + ((lane >> 4) << 3) + (lane & 7)) * 200
                                + ((lane >> 3) & 1) * 8);

    #pragma unroll
    for (int hf = 0; hf < 2; hf++) {
        __syncthreads();   // y/ln2 ready (hf=0) or prev fc2 done (hf=1)
        // load W1 half: rows [hf*192, hf*192+192), stride 104
        for (int gi = tid; gi < 2304; gi += 768) {
            int row = gi / 12, q = gi - row * 12;
            *(uint4*)(sW + row * 104 + q * 8) =
                *(const uint4*)(w1 + (size_t)(hf * 192 + row) * 96 + q * 8);
        }
        __syncthreads();

        // fc1 half: (128x96)@(192x96)^T + bias + GELU -> sHID
        {
            float acc[2][4][4] = {};
            #pragma unroll
            for (int ks = 0; ks < 6; ks++) {
                uint32_t a[2][4], bf[2][4];
                #pragma unroll
                for (int mt = 0; mt < 2; mt++)
                    LDSM_X4(a[mt][0], a[mt][1], a[mt][2], a[mt][3],
                            aln + mt * (16 * 104 * 2) + ks * 32);
                #pragma unroll
                for (int ng = 0; ng < 2; ng++)
                    LDSM_X4(bf[ng][0], bf[ng][1], bf[ng][2], bf[ng][3],
                            bw1 + ng * (16 * 104 * 2) + ks * 32);
                #pragma unroll
                for (int mt = 0; mt < 2; mt++)
                    #pragma unroll
                    for (int nt = 0; nt < 4; nt++) {
                        int ng = nt >> 1, pr = (nt & 1) * 2;
                        MMA_BF16(acc[mt][nt], a[mt][0], a[mt][1], a[mt][2], a[mt][3],
                                 bf[ng][pr], bf[ng][pr + 1]);
                    }
            }
            #pragma unroll
            for (int mt = 0; mt < 2; mt++)
                #pragma unroll
                for (int nt = 0; nt < 4; nt++) {
                    int lr  = wm * 32 + mt * 16 + (lane >> 2);
                    int col = wn * 32 + nt * 8 + (lane & 3) * 2;
                    int gcol = hf * 192 + col;
                    float bf0 = bias1[gcol], bf1 = bias1[gcol + 1];
                    float v0 = acc[mt][nt][0] + bf0, v1 = acc[mt][nt][1] + bf1;
                    float v2 = acc[mt][nt][2] + bf0, v3 = acc[mt][nt][3] + bf1;
                    v0 = 0.5f * v0 * (1.0f + erff(v0 * 0.70710678118654752f));
                    v1 = 0.5f * v1 * (1.0f + erff(v1 * 0.70710678118654752f));
                    v2 = 0.5f * v2 * (1.0f + erff(v2 * 0.70710678118654752f));
                    v3 = 0.5f * v3 * (1.0f + erff(v3 * 0.70710678118654752f));
                    __nv_bfloat162 p0, p1;
                    p0.x = __float2bfloat16(v0); p0.y = __float2bfloat16(v1);
                    p1.x = __float2bfloat16(v2); p1.y = __float2bfloat16(v3);
                    *(__nv_bfloat162*)(sHID + lr * 200 + col)       = p0;
                    *(__nv_bfloat162*)(sHID + (lr + 8) * 200 + col) = p1;
                }
        }
        __syncthreads();

        // load W2 half: 96 rows x cols [hf*192, hf*192+192), stride 200
        for (int gi = tid; gi < 2304; gi += 768) {
            int row = gi / 24, q = gi - row * 24;
            *(uint4*)(sW + row * 200 + q * 8) =
                *(const uint4*)(w2 + (size_t)row * 384 + hf * 192 + q * 8);
        }
        __syncthreads();

        // fc2 partial: (128x192)@(96x192)^T accumulate
        #pragma unroll
        for (int ks = 0; ks < 12; ks++) {
            uint32_t a[2][4], kb[4];
            #pragma unroll
            for (int mt = 0; mt < 2; mt++)
                LDSM_X4(a[mt][0], a[mt][1], a[mt][2], a[mt][3],
                        ah + mt * (16 * 200 * 2) + ks * 32);
            LDSM_X4(kb[0], kb[1], kb[2], kb[3], bw2 + ks * 32);
            #pragma unroll
            for (int mt = 0; mt < 2; mt++) {
                MMA_BF16(acc2[mt][0], a[mt][0], a[mt][1], a[mt][2], a[mt][3], kb[0], kb[1]);
                MMA_BF16(acc2[mt][1], a[mt][0], a[mt][1], a[mt][2], a[mt][3], kb[2], kb[3]);
            }
        }
    }

    // ---- phase 6: out = fc2 + bias2 + y, scatter natural order (fp32) ----
    #pragma unroll
    for (int mt = 0; mt < 2; mt++) {
        #pragma unroll
        for (int hh = 0; hh < 2; hh++) {
            int lr = wm * 32 + mt * 16 + (lane >> 2) + hh * 8;
            int dt = lr >> 6, dh = (lr >> 3) & 7, dw = lr & 7;
            int t = tb * 2 + dt, h = hb * 8 + dh, w = wb * 8 + dw;
            int ti = (t + 1) & 7, hi = (h + 4) & 127, wi = (w + 4) & 127;
            size_t m = ((size_t)((bi * 8 + ti) * 128 + hi)) * 128 + wi;
            #pragma unroll
            for (int nt = 0; nt < 2; nt++) {
                int lc = wn * 16 + nt * 8 + (lane & 3) * 2;
                float v0 = acc2[mt][nt][hh * 2 + 0] + bias2[lc]     + yep[lr * 100 + lc];
                float v1 = acc2[mt][nt][hh * 2 + 1] + bias2[lc + 1] + yep[lr * 100 + lc + 1];
                *(float2*)(out + m * 96 + lc) = make_float2(v0, v1);
            }
        }
    }
}

// ---------------- launch ----------------
extern "C" void kernel_launch(void* const* d_in, const int* in_sizes, int n_in,
                              void* d_out, int out_size)
{
    const float* x      = (const float*)d_in[0];
    const float* g1     = (const float*)d_in[2];
    const float* b1     = (const float*)d_in[3];
    const float* w_qkv  = (const float*)d_in[4];
    const float* b_qkv  = (const float*)d_in[5];
    const float* w_proj = (const float*)d_in[6];
    const float* b_proj = (const float*)d_in[7];
    const float* g2     = (const float*)d_in[8];
    const float* b2     = (const float*)d_in[9];
    const float* w_fc1  = (const float*)d_in[10];
    const float* b_fc1  = (const float*)d_in[11];
    const float* w_fc2  = (const float*)d_in[12];
    const float* b_fc2  = (const float*)d_in[13];
    float* out = (float*)d_out;

    __nv_bfloat16 *p_wb;
    cudaGetSymbolAddress((void**)&p_wb, g_wb);

    static bool attr_set = false;
    if (!attr_set) {
        cudaFuncSetAttribute(mono_kernel,
                             cudaFuncAttributeMaxDynamicSharedMemorySize, SMEM_MONO);
        attr_set = true;
    }

    convert_w<<<(110592 + 255) / 256, 256>>>(w_qkv, w_proj, w_fc1, w_fc2, p_wb);

    mono_kernel<<<NWIN, 768, SMEM_MONO>>>(
        x, g1, b1,
        p_wb + WB_QKV, b_qkv, p_wb + WB_PROJ, b_proj,
        g2, b2,
        p_wb + WB_FC1, b_fc1, p_wb + WB_FC2, b_fc2,
        out);
}